// round 4
// baseline (speedup 1.0000x reference)
#include <cuda_runtime.h>
#include <cuda_bf16.h>

#define BB 64
#define SSEQ 440
#define DDIM 256
#define HN 8
#define FFD 512
#define LNUM 6
#define GP 484          // 22*22
#define BS_ (BB*SSEQ)   // 28160

// ------------ static device scratch (no allocation) ------------
__device__ float g_h[(size_t)BS_*DDIM];
__device__ float g_qkv[(size_t)BS_*3*DDIM];
__device__ float g_t1[(size_t)BS_*FFD];
__device__ float g_t2[(size_t)BS_*DDIM];

// ------------------------ embedding ------------------------
__global__ void k_embed(const int* __restrict__ x,
                        const float* __restrict__ ev, const float* __restrict__ px,
                        const float* __restrict__ py, const float* __restrict__ st,
                        const int* __restrict__ tkx, const int* __restrict__ tky,
                        const int* __restrict__ tks)
{
    int bs = blockIdx.x;
    int s = bs % SSEQ;
    int d = threadIdx.x;
    int xi = x[bs];
    g_h[(size_t)bs*DDIM + d] =
        ev[xi*DDIM + d] + px[tkx[s]*DDIM + d] + py[tky[s]*DDIM + d] + st[tks[s]*DDIM + d];
}

// ---------- SGEMM: C[M,N] = A[M,K] @ W[N,K]^T + bias (opt relu) ----------
__global__ __launch_bounds__(256, 2) void k_gemm(
    const float* __restrict__ A, const float* __restrict__ W,
    const float* __restrict__ bias, float* __restrict__ C,
    int M, int N, int K, int relu)
{
    __shared__ float As[8][132];
    __shared__ float Bs[8][132];
    int tid = threadIdx.x;
    int bm = blockIdx.y * 128, bn = blockIdx.x * 128;
    int lr = tid >> 1;
    int lk = (tid & 1) * 4;
    const float* Ap = A + (size_t)(bm + lr) * K + lk;
    const float* Wp = W + (size_t)(bn + lr) * K + lk;
    float4 a4 = *(const float4*)Ap;
    float4 b4 = *(const float4*)Wp;
    int ty = tid >> 4, tx = tid & 15;
    float acc[8][8];
#pragma unroll
    for (int i = 0; i < 8; i++)
#pragma unroll
        for (int j = 0; j < 8; j++) acc[i][j] = 0.f;
    int nk = K >> 3;
    for (int kt = 0; kt < nk; kt++) {
        As[lk+0][lr] = a4.x; As[lk+1][lr] = a4.y; As[lk+2][lr] = a4.z; As[lk+3][lr] = a4.w;
        Bs[lk+0][lr] = b4.x; Bs[lk+1][lr] = b4.y; Bs[lk+2][lr] = b4.z; Bs[lk+3][lr] = b4.w;
        __syncthreads();
        if (kt + 1 < nk) {
            a4 = *(const float4*)(Ap + (size_t)(kt + 1) * 8);
            b4 = *(const float4*)(Wp + (size_t)(kt + 1) * 8);
        }
#pragma unroll
        for (int k = 0; k < 8; k++) {
            float ar[8], br[8];
            *(float4*)&ar[0] = *(const float4*)&As[k][ty*8];
            *(float4*)&ar[4] = *(const float4*)&As[k][ty*8+4];
            *(float4*)&br[0] = *(const float4*)&Bs[k][tx*8];
            *(float4*)&br[4] = *(const float4*)&Bs[k][tx*8+4];
#pragma unroll
            for (int i = 0; i < 8; i++)
#pragma unroll
                for (int j = 0; j < 8; j++)
                    acc[i][j] = fmaf(ar[i], br[j], acc[i][j]);
        }
        __syncthreads();
    }
#pragma unroll
    for (int i = 0; i < 8; i++) {
        int row = bm + ty*8 + i;
        float* cp = C + (size_t)row*N + bn + tx*8;
        float vv[8];
#pragma unroll
        for (int j = 0; j < 8; j++) {
            float v = acc[i][j] + bias[bn + tx*8 + j];
            if (relu) v = fmaxf(v, 0.f);
            vv[j] = v;
        }
        *(float4*)cp     = make_float4(vv[0], vv[1], vv[2], vv[3]);
        *(float4*)(cp+4) = make_float4(vv[4], vv[5], vv[6], vv[7]);
    }
}

// ------------------- attention: one block per (b,h) -------------------
#define ATTN_SMEM (2*32*448*4)
__global__ __launch_bounds__(256) void k_attn(const float* __restrict__ abias)
{
    extern __shared__ float sm[];
    float* Ks = sm;             // [32][stride 441], alloc 32*448
    float* Vs = sm + 32*448;
    int b = blockIdx.x >> 3, hh = blockIdx.x & 7;
    int tid = threadIdx.x, lane = tid & 31, warp = tid >> 5;
    const float* qkvb = g_qkv + (size_t)b * SSEQ * (3*DDIM);
    for (int idx = tid; idx < SSEQ*32; idx += 256) {
        int s = idx >> 5, d = idx & 31;
        Ks[d*441 + s] = qkvb[(size_t)s*768 + DDIM   + hh*32 + d];
        Vs[d*441 + s] = qkvb[(size_t)s*768 + 2*DDIM + hh*32 + d];
    }
    __syncthreads();
    const float scale = 0.17677669529663687f; // 1/sqrt(32)
    for (int q0 = warp*2; q0 < SSEQ; q0 += 16) {
        float qa = qkvb[(size_t)q0*768 + hh*32 + lane];
        float qb = qkvb[(size_t)(q0+1)*768 + hh*32 + lane];
        float s0[14], s1[14];
#pragma unroll
        for (int kk = 0; kk < 14; kk++) { s0[kk] = 0.f; s1[kk] = 0.f; }
#pragma unroll
        for (int half = 0; half < 2; half++) {
            float qr0[16], qr1[16];
#pragma unroll
            for (int d = 0; d < 16; d++) {
                qr0[d] = __shfl_sync(0xffffffffu, qa, half*16 + d);
                qr1[d] = __shfl_sync(0xffffffffu, qb, half*16 + d);
            }
#pragma unroll
            for (int kk = 0; kk < 14; kk++) {
                int k = kk*32 + lane;
#pragma unroll
                for (int d = 0; d < 16; d++) {
                    float kv = Ks[(half*16 + d)*441 + k];
                    s0[kk] = fmaf(qr0[d], kv, s0[kk]);
                    s1[kk] = fmaf(qr1[d], kv, s1[kk]);
                }
            }
        }
#pragma unroll
        for (int kk = 0; kk < 14; kk++) {
            int k = kk*32 + lane;
            if (k < SSEQ) {
                s0[kk] = fmaf(s0[kk], scale, abias[(size_t)q0*SSEQ + k]);
                s1[kk] = fmaf(s1[kk], scale, abias[(size_t)(q0+1)*SSEQ + k]);
            } else { s0[kk] = -1e30f; s1[kk] = -1e30f; }
        }
        float m0 = -1e30f, m1 = -1e30f;
#pragma unroll
        for (int kk = 0; kk < 14; kk++) { m0 = fmaxf(m0, s0[kk]); m1 = fmaxf(m1, s1[kk]); }
#pragma unroll
        for (int o = 16; o > 0; o >>= 1) {
            m0 = fmaxf(m0, __shfl_xor_sync(~0u, m0, o));
            m1 = fmaxf(m1, __shfl_xor_sync(~0u, m1, o));
        }
        float z0 = 0.f, z1 = 0.f;
#pragma unroll
        for (int kk = 0; kk < 14; kk++) {
            float e0 = __expf(s0[kk] - m0), e1 = __expf(s1[kk] - m1);
            s0[kk] = e0; s1[kk] = e1; z0 += e0; z1 += e1;
        }
#pragma unroll
        for (int o = 16; o > 0; o >>= 1) {
            z0 += __shfl_xor_sync(~0u, z0, o);
            z1 += __shfl_xor_sync(~0u, z1, o);
        }
        float inv0 = 1.f / z0, inv1 = 1.f / z1;
        float out0 = 0.f, out1 = 0.f;
#pragma unroll
        for (int half = 0; half < 2; half++) {
            float a0[16], a1[16];
#pragma unroll
            for (int d = 0; d < 16; d++) { a0[d] = 0.f; a1[d] = 0.f; }
#pragma unroll
            for (int kk = 0; kk < 14; kk++) {
                int k = kk*32 + lane;
                if (k < SSEQ) {
#pragma unroll
                    for (int d = 0; d < 16; d++) {
                        float vv = Vs[(half*16 + d)*441 + k];
                        a0[d] = fmaf(s0[kk], vv, a0[d]);
                        a1[d] = fmaf(s1[kk], vv, a1[d]);
                    }
                }
            }
#pragma unroll
            for (int o = 16; o > 0; o >>= 1) {
#pragma unroll
                for (int d = 0; d < 16; d++) {
                    a0[d] += __shfl_xor_sync(~0u, a0[d], o);
                    a1[d] += __shfl_xor_sync(~0u, a1[d], o);
                }
            }
#pragma unroll
            for (int d = 0; d < 16; d++) {
                if (lane == half*16 + d) { out0 = a0[d]*inv0; out1 = a1[d]*inv1; }
            }
        }
        g_t1[((size_t)b*SSEQ + q0)*DDIM + hh*32 + lane]     = out0;
        g_t1[((size_t)b*SSEQ + q0 + 1)*DDIM + hh*32 + lane] = out1;
    }
}

// ------------- fused residual + layernorm (in place on g_h) -------------
__global__ __launch_bounds__(256) void k_ln(const float* __restrict__ add,
                                            const float* __restrict__ gam,
                                            const float* __restrict__ bet)
{
    int r = blockIdx.x, d = threadIdx.x;
    size_t i = (size_t)r*DDIM + d;
    float v = g_h[i] + add[i];
    float s1 = v, s2 = v*v;
#pragma unroll
    for (int o = 16; o > 0; o >>= 1) {
        s1 += __shfl_xor_sync(~0u, s1, o);
        s2 += __shfl_xor_sync(~0u, s2, o);
    }
    __shared__ float a1s[8], a2s[8];
    if ((d & 31) == 0) { a1s[d>>5] = s1; a2s[d>>5] = s2; }
    __syncthreads();
    float t1 = 0.f, t2 = 0.f;
#pragma unroll
    for (int j = 0; j < 8; j++) { t1 += a1s[j]; t2 += a2s[j]; }
    float m = t1 * (1.f/256.f);
    float var = t2 * (1.f/256.f) - m*m;
    g_h[i] = (v - m) * rsqrtf(var + 1e-5f) * gam[d] + bet[d];
}

// --------- fused grid-scatter + 3 dilated grouped convs + gather ---------
// one block per (b, group of 32 channels); in-place on disjoint slices
#define CONV_SMEM ((32*484 + 32*32*9)*4)
__global__ __launch_bounds__(256) void k_conv(
    const float* __restrict__ cw1, const float* __restrict__ cb1,
    const float* __restrict__ cw2, const float* __restrict__ cb2,
    const float* __restrict__ cw3, const float* __restrict__ cb3,
    float* __restrict__ out)
{
    extern __shared__ float sm[];
    float* sx = sm;              // [32 ch][484]
    float* sw = sm + 32*484;     // [32 oc][32 ic][9]
    int b = blockIdx.x >> 3, grp = blockIdx.x & 7;
    int tid = threadIdx.x, lane = tid & 31, warp = tid >> 5;
    const float* hb = g_h + (size_t)b * SSEQ * DDIM;

    for (int p = warp; p < 484; p += 8) {
        float v = (p < SSEQ) ? hb[(size_t)p*DDIM + grp*32 + lane] : 0.f;
        sx[lane*484 + p] = v;
    }

    int ocb = warp * 4;
    float tot[7][2][4];
#pragma unroll
    for (int it = 0; it < 7; it++)
#pragma unroll
        for (int pr = 0; pr < 2; pr++)
#pragma unroll
            for (int j = 0; j < 4; j++) tot[it][pr][j] = 0.f;

    const float* cws[3] = {cw1, cw2, cw3};
    const float* cbs[3] = {cb1, cb2, cb3};

    for (int cv = 0; cv < 3; cv++) {
        int dil = cv + 1;
        __syncthreads();
        const float* src = cws[cv] + (size_t)grp * 32 * 288;
        for (int i = tid; i < 32*288; i += 256) sw[i] = src[i];
        __syncthreads();
        float cbv[4];
#pragma unroll
        for (int j = 0; j < 4; j++) cbv[j] = cbs[cv][grp*32 + ocb + j];

#pragma unroll
        for (int it = 0; it < 7; it++) {
            int pxA = lane + 32*it;
            int pxB = pxA + 224;
            int rA = pxA / 22, cA = pxA % 22;
            int rB = pxB / 22, cB = pxB % 22;
            int offA[9], offB[9];
            int t = 0;
#pragma unroll
            for (int dr = -1; dr <= 1; dr++)
#pragma unroll
                for (int dc = -1; dc <= 1; dc++) {
                    int ri = rA + dil*dr, ci = cA + dil*dc;
                    offA[t] = (ri >= 0 && ri < 22 && ci >= 0 && ci < 22) ? ri*22 + ci : -1;
                    ri = rB + dil*dr; ci = cB + dil*dc;
                    offB[t] = (pxB < SSEQ && ri >= 0 && ri < 22 && ci >= 0 && ci < 22) ? ri*22 + ci : -1;
                    t++;
                }
            float accA[4] = {0.f, 0.f, 0.f, 0.f};
            float accB[4] = {0.f, 0.f, 0.f, 0.f};
            for (int ic = 0; ic < 32; ic++) {
                const float* xb = sx + ic*484;
                float xvA[9], xvB[9];
#pragma unroll
                for (int tt = 0; tt < 9; tt++) {
                    xvA[tt] = (offA[tt] >= 0) ? xb[offA[tt]] : 0.f;
                    xvB[tt] = (offB[tt] >= 0) ? xb[offB[tt]] : 0.f;
                }
#pragma unroll
                for (int j = 0; j < 4; j++) {
                    const float* wj = sw + (ocb + j)*288 + ic*9;
#pragma unroll
                    for (int tt = 0; tt < 9; tt++) {
                        float w = wj[tt];
                        accA[j] = fmaf(w, xvA[tt], accA[j]);
                        accB[j] = fmaf(w, xvB[tt], accB[j]);
                    }
                }
            }
#pragma unroll
            for (int j = 0; j < 4; j++) {
                tot[it][0][j] += fmaxf(accA[j] + cbv[j], 0.f);
                tot[it][1][j] += fmaxf(accB[j] + cbv[j], 0.f);
            }
        }
    }

    float* ob = out + (size_t)b * SSEQ * DDIM;
#pragma unroll
    for (int it = 0; it < 7; it++) {
#pragma unroll
        for (int pr = 0; pr < 2; pr++) {
            int px = lane + 32*it + 224*pr;
            if (px < SSEQ) {
#pragma unroll
                for (int j = 0; j < 4; j++) {
                    int oc = ocb + j;
                    ob[(size_t)px*DDIM + grp*32 + oc] =
                        0.5f * (sx[oc*484 + px] + tot[it][pr][j]);
                }
            }
        }
    }
}

// ------------------------------ launcher ------------------------------
extern "C" void kernel_launch(void* const* d_in, const int* in_sizes, int n_in,
                              void* d_out, int out_size)
{
    const int* x    = (const int*)d_in[0];
    // d_in[1]: scatter_positions (identity s = r*22+c) — unused
    const float* ev   = (const float*)d_in[2];
    const float* px   = (const float*)d_in[3];
    const float* py   = (const float*)d_in[4];
    const float* st   = (const float*)d_in[5];
    const int* tkx = (const int*)d_in[6];
    const int* tky = (const int*)d_in[7];
    const int* tks = (const int*)d_in[8];
    const float* abias = (const float*)d_in[9];
    const float* Wqkv = (const float*)d_in[10];
    const float* bqkv = (const float*)d_in[11];
    const float* Wo   = (const float*)d_in[12];
    const float* bo   = (const float*)d_in[13];
    const float* W1   = (const float*)d_in[14];
    const float* b1   = (const float*)d_in[15];
    const float* W2   = (const float*)d_in[16];
    const float* b2   = (const float*)d_in[17];
    const float* ln1s = (const float*)d_in[18];
    const float* ln1b = (const float*)d_in[19];
    const float* ln2s = (const float*)d_in[20];
    const float* ln2b = (const float*)d_in[21];
    const float* cw1  = (const float*)d_in[22];
    const float* cb1  = (const float*)d_in[23];
    const float* cw2  = (const float*)d_in[24];
    const float* cb2  = (const float*)d_in[25];
    const float* cw3  = (const float*)d_in[26];
    const float* cb3  = (const float*)d_in[27];
    float* out = (float*)d_out;

    float *hP, *qkvP, *t1P, *t2P;
    cudaGetSymbolAddress((void**)&hP,   g_h);
    cudaGetSymbolAddress((void**)&qkvP, g_qkv);
    cudaGetSymbolAddress((void**)&t1P,  g_t1);
    cudaGetSymbolAddress((void**)&t2P,  g_t2);

    cudaFuncSetAttribute(k_attn, cudaFuncAttributeMaxDynamicSharedMemorySize, ATTN_SMEM);
    cudaFuncSetAttribute(k_conv, cudaFuncAttributeMaxDynamicSharedMemorySize, CONV_SMEM);

    k_embed<<<BS_, 256>>>(x, ev, px, py, st, tkx, tky, tks);

    for (int l = 0; l < LNUM; l++) {
        // QKV
        k_gemm<<<dim3(6, 220), 256>>>(hP, Wqkv + (size_t)l*768*256, bqkv + l*768,
                                      qkvP, BS_, 768, 256, 0);
        // attention -> g_t1
        k_attn<<<BB*HN, 256, ATTN_SMEM>>>(abias);
        // Wo
        k_gemm<<<dim3(2, 220), 256>>>(t1P, Wo + (size_t)l*256*256, bo + l*256,
                                      t2P, BS_, 256, 256, 0);
        k_ln<<<BS_, 256>>>(t2P, ln1s + l*256, ln1b + l*256);
        // FF
        k_gemm<<<dim3(4, 220), 256>>>(hP, W1 + (size_t)l*512*256, b1 + l*512,
                                      t1P, BS_, 512, 256, 1);
        k_gemm<<<dim3(2, 220), 256>>>(t1P, W2 + (size_t)l*256*512, b2 + l*256,
                                      t2P, BS_, 256, 512, 0);
        k_ln<<<BS_, 256>>>(t2P, ln2s + l*256, ln2b + l*256);
        // conv block (writes d_out on the last layer)
        float* cout = (l == LNUM-1) ? out : hP;
        k_conv<<<BB*HN, 256, CONV_SMEM>>>(cw1 + (size_t)l*256*288, cb1 + l*256,
                                          cw2 + (size_t)l*256*288, cb2 + l*256,
                                          cw3 + (size_t)l*256*288, cb3 + l*256,
                                          cout);
    }
}

// round 5
// speedup vs baseline: 1.1608x; 1.1608x over previous
#include <cuda_runtime.h>
#include <cuda_bf16.h>

#define BB 64
#define SSEQ 440
#define DDIM 256
#define HN 8
#define FFD 512
#define LNUM 6
#define GP 484          // 22*22
#define BS_ (BB*SSEQ)   // 28160

// ------------ static device scratch (no allocation) ------------
__device__ float g_h[(size_t)BS_*DDIM];
__device__ float g_qkv[(size_t)BS_*3*DDIM];
__device__ float g_t1[(size_t)BS_*FFD];
__device__ float g_t2[(size_t)BS_*DDIM];

__device__ __forceinline__ unsigned f2tf(float f) {
    unsigned u;
    asm("cvt.rna.tf32.f32 %0, %1;" : "=r"(u) : "f"(f));
    return u;
}

// ------------------------ embedding ------------------------
__global__ void k_embed(const int* __restrict__ x,
                        const float* __restrict__ ev, const float* __restrict__ px,
                        const float* __restrict__ py, const float* __restrict__ st,
                        const int* __restrict__ tkx, const int* __restrict__ tky,
                        const int* __restrict__ tks)
{
    int bs = blockIdx.x;
    int s = bs % SSEQ;
    int d = threadIdx.x;
    int xi = x[bs];
    g_h[(size_t)bs*DDIM + d] =
        ev[xi*DDIM + d] + px[tkx[s]*DDIM + d] + py[tky[s]*DDIM + d] + st[tks[s]*DDIM + d];
}

// ---- TF32 tensor-core GEMM: C[M,N] = A[M,K] @ W[N,K]^T + bias (opt relu) ----
// 128x128 tile, k-step 16, 8 warps each computing 64x32 via m16n8k8 mma
__global__ __launch_bounds__(256, 2) void k_gemm(
    const float* __restrict__ A, const float* __restrict__ W,
    const float* __restrict__ bias, float* __restrict__ C,
    int M, int N, int K, int relu)
{
    __shared__ unsigned As[128][20];   // [m][k] pad->bank-stride 20 (conflict-free)
    __shared__ unsigned Bs[128][20];   // [n][k]
    int tid = threadIdx.x;
    int bm = blockIdx.y * 128, bn = blockIdx.x * 128;
    int row = tid >> 1, kq = (tid & 1) * 8;
    const float* Ap = A + (size_t)(bm + row) * K + kq;
    const float* Wp = W + (size_t)(bn + row) * K + kq;
    float4 pa0 = *(const float4*)Ap;
    float4 pa1 = *(const float4*)(Ap + 4);
    float4 pb0 = *(const float4*)Wp;
    float4 pb1 = *(const float4*)(Wp + 4);

    int lane = tid & 31, warp = tid >> 5;
    int wm = (warp & 1) * 64, wn = (warp >> 1) * 32;
    int grp = lane >> 2, qd = lane & 3;

    float c[4][4][4];
#pragma unroll
    for (int mt = 0; mt < 4; mt++)
#pragma unroll
        for (int nt = 0; nt < 4; nt++)
#pragma unroll
            for (int r = 0; r < 4; r++) c[mt][nt][r] = 0.f;

    int nk = K >> 4;
    for (int kt = 0; kt < nk; kt++) {
        *(uint4*)&As[row][kq]     = make_uint4(f2tf(pa0.x), f2tf(pa0.y), f2tf(pa0.z), f2tf(pa0.w));
        *(uint4*)&As[row][kq + 4] = make_uint4(f2tf(pa1.x), f2tf(pa1.y), f2tf(pa1.z), f2tf(pa1.w));
        *(uint4*)&Bs[row][kq]     = make_uint4(f2tf(pb0.x), f2tf(pb0.y), f2tf(pb0.z), f2tf(pb0.w));
        *(uint4*)&Bs[row][kq + 4] = make_uint4(f2tf(pb1.x), f2tf(pb1.y), f2tf(pb1.z), f2tf(pb1.w));
        __syncthreads();
        if (kt + 1 < nk) {
            const float* Ap2 = Ap + (size_t)(kt + 1) * 16;
            const float* Wp2 = Wp + (size_t)(kt + 1) * 16;
            pa0 = *(const float4*)Ap2; pa1 = *(const float4*)(Ap2 + 4);
            pb0 = *(const float4*)Wp2; pb1 = *(const float4*)(Wp2 + 4);
        }
#pragma unroll
        for (int kh = 0; kh < 16; kh += 8) {
            unsigned af[4][4], bf[4][2];
#pragma unroll
            for (int mt = 0; mt < 4; mt++) {
                int r0 = wm + mt*16 + grp;
                af[mt][0] = As[r0][kh + qd];
                af[mt][1] = As[r0 + 8][kh + qd];
                af[mt][2] = As[r0][kh + qd + 4];
                af[mt][3] = As[r0 + 8][kh + qd + 4];
            }
#pragma unroll
            for (int nt = 0; nt < 4; nt++) {
                int n0 = wn + nt*8 + grp;
                bf[nt][0] = Bs[n0][kh + qd];
                bf[nt][1] = Bs[n0][kh + qd + 4];
            }
#pragma unroll
            for (int mt = 0; mt < 4; mt++)
#pragma unroll
                for (int nt = 0; nt < 4; nt++) {
                    asm volatile(
                        "mma.sync.aligned.m16n8k8.row.col.f32.tf32.tf32.f32 "
                        "{%0,%1,%2,%3}, {%4,%5,%6,%7}, {%8,%9}, {%0,%1,%2,%3};"
                        : "+f"(c[mt][nt][0]), "+f"(c[mt][nt][1]),
                          "+f"(c[mt][nt][2]), "+f"(c[mt][nt][3])
                        : "r"(af[mt][0]), "r"(af[mt][1]), "r"(af[mt][2]), "r"(af[mt][3]),
                          "r"(bf[nt][0]), "r"(bf[nt][1]));
                }
        }
        __syncthreads();
    }

    // epilogue: bias (+relu), vectorized float2 stores
#pragma unroll
    for (int mt = 0; mt < 4; mt++) {
        int r0 = bm + wm + mt*16 + grp;
#pragma unroll
        for (int nt = 0; nt < 4; nt++) {
            int cb = bn + wn + nt*8 + 2*qd;
            float bi0 = bias[cb], bi1 = bias[cb + 1];
            float v0 = c[mt][nt][0] + bi0;
            float v1 = c[mt][nt][1] + bi1;
            float v2 = c[mt][nt][2] + bi0;
            float v3 = c[mt][nt][3] + bi1;
            if (relu) {
                v0 = fmaxf(v0, 0.f); v1 = fmaxf(v1, 0.f);
                v2 = fmaxf(v2, 0.f); v3 = fmaxf(v3, 0.f);
            }
            *(float2*)(C + (size_t)r0*N + cb)       = make_float2(v0, v1);
            *(float2*)(C + (size_t)(r0 + 8)*N + cb) = make_float2(v2, v3);
        }
    }
}

// ------------------- attention: one block per (b,h) -------------------
#define ATTN_SMEM (2*32*448*4)
__global__ __launch_bounds__(256) void k_attn(const float* __restrict__ abias)
{
    extern __shared__ float sm[];
    float* Ks = sm;             // [32][stride 441], alloc 32*448
    float* Vs = sm + 32*448;
    int b = blockIdx.x >> 3, hh = blockIdx.x & 7;
    int tid = threadIdx.x, lane = tid & 31, warp = tid >> 5;
    const float* qkvb = g_qkv + (size_t)b * SSEQ * (3*DDIM);
    for (int idx = tid; idx < SSEQ*32; idx += 256) {
        int s = idx >> 5, d = idx & 31;
        Ks[d*441 + s] = qkvb[(size_t)s*768 + DDIM   + hh*32 + d];
        Vs[d*441 + s] = qkvb[(size_t)s*768 + 2*DDIM + hh*32 + d];
    }
    __syncthreads();
    const float scale = 0.17677669529663687f; // 1/sqrt(32)
    for (int q0 = warp*2; q0 < SSEQ; q0 += 16) {
        float qa = qkvb[(size_t)q0*768 + hh*32 + lane];
        float qb = qkvb[(size_t)(q0+1)*768 + hh*32 + lane];
        float s0[14], s1[14];
#pragma unroll
        for (int kk = 0; kk < 14; kk++) { s0[kk] = 0.f; s1[kk] = 0.f; }
#pragma unroll
        for (int half = 0; half < 2; half++) {
            float qr0[16], qr1[16];
#pragma unroll
            for (int d = 0; d < 16; d++) {
                qr0[d] = __shfl_sync(0xffffffffu, qa, half*16 + d);
                qr1[d] = __shfl_sync(0xffffffffu, qb, half*16 + d);
            }
#pragma unroll
            for (int kk = 0; kk < 14; kk++) {
                int k = kk*32 + lane;
#pragma unroll
                for (int d = 0; d < 16; d++) {
                    float kv = Ks[(half*16 + d)*441 + k];
                    s0[kk] = fmaf(qr0[d], kv, s0[kk]);
                    s1[kk] = fmaf(qr1[d], kv, s1[kk]);
                }
            }
        }
#pragma unroll
        for (int kk = 0; kk < 14; kk++) {
            int k = kk*32 + lane;
            if (k < SSEQ) {
                s0[kk] = fmaf(s0[kk], scale, abias[(size_t)q0*SSEQ + k]);
                s1[kk] = fmaf(s1[kk], scale, abias[(size_t)(q0+1)*SSEQ + k]);
            } else { s0[kk] = -1e30f; s1[kk] = -1e30f; }
        }
        float m0 = -1e30f, m1 = -1e30f;
#pragma unroll
        for (int kk = 0; kk < 14; kk++) { m0 = fmaxf(m0, s0[kk]); m1 = fmaxf(m1, s1[kk]); }
#pragma unroll
        for (int o = 16; o > 0; o >>= 1) {
            m0 = fmaxf(m0, __shfl_xor_sync(~0u, m0, o));
            m1 = fmaxf(m1, __shfl_xor_sync(~0u, m1, o));
        }
        float z0 = 0.f, z1 = 0.f;
#pragma unroll
        for (int kk = 0; kk < 14; kk++) {
            float e0 = __expf(s0[kk] - m0), e1 = __expf(s1[kk] - m1);
            s0[kk] = e0; s1[kk] = e1; z0 += e0; z1 += e1;
        }
#pragma unroll
        for (int o = 16; o > 0; o >>= 1) {
            z0 += __shfl_xor_sync(~0u, z0, o);
            z1 += __shfl_xor_sync(~0u, z1, o);
        }
        float inv0 = 1.f / z0, inv1 = 1.f / z1;
        float out0 = 0.f, out1 = 0.f;
#pragma unroll
        for (int half = 0; half < 2; half++) {
            float a0[16], a1[16];
#pragma unroll
            for (int d = 0; d < 16; d++) { a0[d] = 0.f; a1[d] = 0.f; }
#pragma unroll
            for (int kk = 0; kk < 14; kk++) {
                int k = kk*32 + lane;
                if (k < SSEQ) {
#pragma unroll
                    for (int d = 0; d < 16; d++) {
                        float vv = Vs[(half*16 + d)*441 + k];
                        a0[d] = fmaf(s0[kk], vv, a0[d]);
                        a1[d] = fmaf(s1[kk], vv, a1[d]);
                    }
                }
            }
#pragma unroll
            for (int o = 16; o > 0; o >>= 1) {
#pragma unroll
                for (int d = 0; d < 16; d++) {
                    a0[d] += __shfl_xor_sync(~0u, a0[d], o);
                    a1[d] += __shfl_xor_sync(~0u, a1[d], o);
                }
            }
#pragma unroll
            for (int d = 0; d < 16; d++) {
                if (lane == half*16 + d) { out0 = a0[d]*inv0; out1 = a1[d]*inv1; }
            }
        }
        g_t1[((size_t)b*SSEQ + q0)*DDIM + hh*32 + lane]     = out0;
        g_t1[((size_t)b*SSEQ + q0 + 1)*DDIM + hh*32 + lane] = out1;
    }
}

// ------------- fused residual + layernorm (in place on g_h) -------------
__global__ __launch_bounds__(256) void k_ln(const float* __restrict__ add,
                                            const float* __restrict__ gam,
                                            const float* __restrict__ bet)
{
    int r = blockIdx.x, d = threadIdx.x;
    size_t i = (size_t)r*DDIM + d;
    float v = g_h[i] + add[i];
    float s1 = v, s2 = v*v;
#pragma unroll
    for (int o = 16; o > 0; o >>= 1) {
        s1 += __shfl_xor_sync(~0u, s1, o);
        s2 += __shfl_xor_sync(~0u, s2, o);
    }
    __shared__ float a1s[8], a2s[8];
    if ((d & 31) == 0) { a1s[d>>5] = s1; a2s[d>>5] = s2; }
    __syncthreads();
    float t1 = 0.f, t2 = 0.f;
#pragma unroll
    for (int j = 0; j < 8; j++) { t1 += a1s[j]; t2 += a2s[j]; }
    float m = t1 * (1.f/256.f);
    float var = t2 * (1.f/256.f) - m*m;
    g_h[i] = (v - m) * rsqrtf(var + 1e-5f) * gam[d] + bet[d];
}

// --------- fused grid-scatter + 3 dilated grouped convs + gather ---------
// one block per (b, group of 32 channels); in-place on disjoint slices
#define CONV_SMEM ((32*484 + 32*32*9)*4)
__global__ __launch_bounds__(256) void k_conv(
    const float* __restrict__ cw1, const float* __restrict__ cb1,
    const float* __restrict__ cw2, const float* __restrict__ cb2,
    const float* __restrict__ cw3, const float* __restrict__ cb3,
    float* __restrict__ out)
{
    extern __shared__ float sm[];
    float* sx = sm;              // [32 ch][484]
    float* sw = sm + 32*484;     // [32 oc][32 ic][9]
    int b = blockIdx.x >> 3, grp = blockIdx.x & 7;
    int tid = threadIdx.x, lane = tid & 31, warp = tid >> 5;
    const float* hb = g_h + (size_t)b * SSEQ * DDIM;

    for (int p = warp; p < 484; p += 8) {
        float v = (p < SSEQ) ? hb[(size_t)p*DDIM + grp*32 + lane] : 0.f;
        sx[lane*484 + p] = v;
    }

    int ocb = warp * 4;
    float tot[7][2][4];
#pragma unroll
    for (int it = 0; it < 7; it++)
#pragma unroll
        for (int pr = 0; pr < 2; pr++)
#pragma unroll
            for (int j = 0; j < 4; j++) tot[it][pr][j] = 0.f;

    const float* cws[3] = {cw1, cw2, cw3};
    const float* cbs[3] = {cb1, cb2, cb3};

    for (int cv = 0; cv < 3; cv++) {
        int dil = cv + 1;
        __syncthreads();
        const float* src = cws[cv] + (size_t)grp * 32 * 288;
        for (int i = tid; i < 32*288; i += 256) sw[i] = src[i];
        __syncthreads();
        float cbv[4];
#pragma unroll
        for (int j = 0; j < 4; j++) cbv[j] = cbs[cv][grp*32 + ocb + j];

#pragma unroll
        for (int it = 0; it < 7; it++) {
            int pxA = lane + 32*it;
            int pxB = pxA + 224;
            int rA = pxA / 22, cA = pxA % 22;
            int rB = pxB / 22, cB = pxB % 22;
            int offA[9], offB[9];
            int t = 0;
#pragma unroll
            for (int dr = -1; dr <= 1; dr++)
#pragma unroll
                for (int dc = -1; dc <= 1; dc++) {
                    int ri = rA + dil*dr, ci = cA + dil*dc;
                    offA[t] = (ri >= 0 && ri < 22 && ci >= 0 && ci < 22) ? ri*22 + ci : -1;
                    ri = rB + dil*dr; ci = cB + dil*dc;
                    offB[t] = (pxB < SSEQ && ri >= 0 && ri < 22 && ci >= 0 && ci < 22) ? ri*22 + ci : -1;
                    t++;
                }
            float accA[4] = {0.f, 0.f, 0.f, 0.f};
            float accB[4] = {0.f, 0.f, 0.f, 0.f};
            for (int ic = 0; ic < 32; ic++) {
                const float* xb = sx + ic*484;
                float xvA[9], xvB[9];
#pragma unroll
                for (int tt = 0; tt < 9; tt++) {
                    xvA[tt] = (offA[tt] >= 0) ? xb[offA[tt]] : 0.f;
                    xvB[tt] = (offB[tt] >= 0) ? xb[offB[tt]] : 0.f;
                }
#pragma unroll
                for (int j = 0; j < 4; j++) {
                    const float* wj = sw + (ocb + j)*288 + ic*9;
#pragma unroll
                    for (int tt = 0; tt < 9; tt++) {
                        float w = wj[tt];
                        accA[j] = fmaf(w, xvA[tt], accA[j]);
                        accB[j] = fmaf(w, xvB[tt], accB[j]);
                    }
                }
            }
#pragma unroll
            for (int j = 0; j < 4; j++) {
                tot[it][0][j] += fmaxf(accA[j] + cbv[j], 0.f);
                tot[it][1][j] += fmaxf(accB[j] + cbv[j], 0.f);
            }
        }
    }

    float* ob = out + (size_t)b * SSEQ * DDIM;
#pragma unroll
    for (int it = 0; it < 7; it++) {
#pragma unroll
        for (int pr = 0; pr < 2; pr++) {
            int px = lane + 32*it + 224*pr;
            if (px < SSEQ) {
#pragma unroll
                for (int j = 0; j < 4; j++) {
                    int oc = ocb + j;
                    ob[(size_t)px*DDIM + grp*32 + oc] =
                        0.5f * (sx[oc*484 + px] + tot[it][pr][j]);
                }
            }
        }
    }
}

// ------------------------------ launcher ------------------------------
extern "C" void kernel_launch(void* const* d_in, const int* in_sizes, int n_in,
                              void* d_out, int out_size)
{
    const int* x    = (const int*)d_in[0];
    // d_in[1]: scatter_positions (identity s = r*22+c) — unused
    const float* ev   = (const float*)d_in[2];
    const float* px   = (const float*)d_in[3];
    const float* py   = (const float*)d_in[4];
    const float* st   = (const float*)d_in[5];
    const int* tkx = (const int*)d_in[6];
    const int* tky = (const int*)d_in[7];
    const int* tks = (const int*)d_in[8];
    const float* abias = (const float*)d_in[9];
    const float* Wqkv = (const float*)d_in[10];
    const float* bqkv = (const float*)d_in[11];
    const float* Wo   = (const float*)d_in[12];
    const float* bo   = (const float*)d_in[13];
    const float* W1   = (const float*)d_in[14];
    const float* b1   = (const float*)d_in[15];
    const float* W2   = (const float*)d_in[16];
    const float* b2   = (const float*)d_in[17];
    const float* ln1s = (const float*)d_in[18];
    const float* ln1b = (const float*)d_in[19];
    const float* ln2s = (const float*)d_in[20];
    const float* ln2b = (const float*)d_in[21];
    const float* cw1  = (const float*)d_in[22];
    const float* cb1  = (const float*)d_in[23];
    const float* cw2  = (const float*)d_in[24];
    const float* cb2  = (const float*)d_in[25];
    const float* cw3  = (const float*)d_in[26];
    const float* cb3  = (const float*)d_in[27];
    float* out = (float*)d_out;

    float *hP, *qkvP, *t1P, *t2P;
    cudaGetSymbolAddress((void**)&hP,   g_h);
    cudaGetSymbolAddress((void**)&qkvP, g_qkv);
    cudaGetSymbolAddress((void**)&t1P,  g_t1);
    cudaGetSymbolAddress((void**)&t2P,  g_t2);

    cudaFuncSetAttribute(k_attn, cudaFuncAttributeMaxDynamicSharedMemorySize, ATTN_SMEM);
    cudaFuncSetAttribute(k_conv, cudaFuncAttributeMaxDynamicSharedMemorySize, CONV_SMEM);

    k_embed<<<BS_, 256>>>(x, ev, px, py, st, tkx, tky, tks);

    for (int l = 0; l < LNUM; l++) {
        // QKV
        k_gemm<<<dim3(6, 220), 256>>>(hP, Wqkv + (size_t)l*768*256, bqkv + l*768,
                                      qkvP, BS_, 768, 256, 0);
        // attention -> g_t1
        k_attn<<<BB*HN, 256, ATTN_SMEM>>>(abias);
        // Wo
        k_gemm<<<dim3(2, 220), 256>>>(t1P, Wo + (size_t)l*256*256, bo + l*256,
                                      t2P, BS_, 256, 256, 0);
        k_ln<<<BS_, 256>>>(t2P, ln1s + l*256, ln1b + l*256);
        // FF
        k_gemm<<<dim3(4, 220), 256>>>(hP, W1 + (size_t)l*512*256, b1 + l*512,
                                      t1P, BS_, 512, 256, 1);
        k_gemm<<<dim3(2, 220), 256>>>(t1P, W2 + (size_t)l*256*512, b2 + l*256,
                                      t2P, BS_, 256, 512, 0);
        k_ln<<<BS_, 256>>>(t2P, ln2s + l*256, ln2b + l*256);
        // conv block (writes d_out on the last layer)
        float* cout = (l == LNUM-1) ? out : hP;
        k_conv<<<BB*HN, 256, CONV_SMEM>>>(cw1 + (size_t)l*256*288, cb1 + l*256,
                                          cw2 + (size_t)l*256*288, cb2 + l*256,
                                          cw3 + (size_t)l*256*288, cb3 + l*256,
                                          cout);
    }
}

// round 7
// speedup vs baseline: 1.5194x; 1.3089x over previous
#include <cuda_runtime.h>
#include <cuda_bf16.h>

#define BB 64
#define SSEQ 440
#define DDIM 256
#define HN 8
#define FFD 512
#define LNUM 6
#define GP 484          // 22*22
#define BS_ (BB*SSEQ)   // 28160

// ------------ static device scratch (no allocation) ------------
__device__ float g_h[(size_t)BS_*DDIM];
__device__ float g_qkv[(size_t)BS_*3*DDIM];
__device__ float g_t1[(size_t)BS_*FFD];
__device__ float g_t2[(size_t)BS_*DDIM];

__device__ __forceinline__ unsigned f2tf(float f) {
    unsigned u;
    asm("cvt.rna.tf32.f32 %0, %1;" : "=r"(u) : "f"(f));
    return u;
}

__device__ __forceinline__ void mma_tf32(float& c0, float& c1, float& c2, float& c3,
                                         unsigned a0, unsigned a1, unsigned a2, unsigned a3,
                                         unsigned b0, unsigned b1)
{
    asm volatile(
        "mma.sync.aligned.m16n8k8.row.col.f32.tf32.tf32.f32 "
        "{%0,%1,%2,%3}, {%4,%5,%6,%7}, {%8,%9}, {%0,%1,%2,%3};"
        : "+f"(c0), "+f"(c1), "+f"(c2), "+f"(c3)
        : "r"(a0), "r"(a1), "r"(a2), "r"(a3), "r"(b0), "r"(b1));
}

// ------------------------ embedding ------------------------
__global__ void k_embed(const int* __restrict__ x,
                        const float* __restrict__ ev, const float* __restrict__ px,
                        const float* __restrict__ py, const float* __restrict__ st,
                        const int* __restrict__ tkx, const int* __restrict__ tky,
                        const int* __restrict__ tks)
{
    int bs = blockIdx.x;
    int s = bs % SSEQ;
    int d = threadIdx.x;
    int xi = x[bs];
    g_h[(size_t)bs*DDIM + d] =
        ev[xi*DDIM + d] + px[tkx[s]*DDIM + d] + py[tky[s]*DDIM + d] + st[tks[s]*DDIM + d];
}

// ---- TF32 tensor-core GEMM: C[M,N] = A[M,K] @ W[N,K]^T + bias (opt relu) ----
__global__ __launch_bounds__(256, 2) void k_gemm(
    const float* __restrict__ A, const float* __restrict__ W,
    const float* __restrict__ bias, float* __restrict__ C,
    int M, int N, int K, int relu)
{
    __shared__ unsigned As[128][20];
    __shared__ unsigned Bs[128][20];
    int tid = threadIdx.x;
    int bm = blockIdx.y * 128, bn = blockIdx.x * 128;
    int row = tid >> 1, kq = (tid & 1) * 8;
    const float* Ap = A + (size_t)(bm + row) * K + kq;
    const float* Wp = W + (size_t)(bn + row) * K + kq;
    float4 pa0 = *(const float4*)Ap;
    float4 pa1 = *(const float4*)(Ap + 4);
    float4 pb0 = *(const float4*)Wp;
    float4 pb1 = *(const float4*)(Wp + 4);

    int lane = tid & 31, warp = tid >> 5;
    int wm = (warp & 1) * 64, wn = (warp >> 1) * 32;
    int grp = lane >> 2, qd = lane & 3;

    float c[4][4][4];
#pragma unroll
    for (int mt = 0; mt < 4; mt++)
#pragma unroll
        for (int nt = 0; nt < 4; nt++)
#pragma unroll
            for (int r = 0; r < 4; r++) c[mt][nt][r] = 0.f;

    int nk = K >> 4;
    for (int kt = 0; kt < nk; kt++) {
        *(uint4*)&As[row][kq]     = make_uint4(f2tf(pa0.x), f2tf(pa0.y), f2tf(pa0.z), f2tf(pa0.w));
        *(uint4*)&As[row][kq + 4] = make_uint4(f2tf(pa1.x), f2tf(pa1.y), f2tf(pa1.z), f2tf(pa1.w));
        *(uint4*)&Bs[row][kq]     = make_uint4(f2tf(pb0.x), f2tf(pb0.y), f2tf(pb0.z), f2tf(pb0.w));
        *(uint4*)&Bs[row][kq + 4] = make_uint4(f2tf(pb1.x), f2tf(pb1.y), f2tf(pb1.z), f2tf(pb1.w));
        __syncthreads();
        if (kt + 1 < nk) {
            const float* Ap2 = Ap + (size_t)(kt + 1) * 16;
            const float* Wp2 = Wp + (size_t)(kt + 1) * 16;
            pa0 = *(const float4*)Ap2; pa1 = *(const float4*)(Ap2 + 4);
            pb0 = *(const float4*)Wp2; pb1 = *(const float4*)(Wp2 + 4);
        }
#pragma unroll
        for (int kh = 0; kh < 16; kh += 8) {
            unsigned af[4][4], bf[4][2];
#pragma unroll
            for (int mt = 0; mt < 4; mt++) {
                int r0 = wm + mt*16 + grp;
                af[mt][0] = As[r0][kh + qd];
                af[mt][1] = As[r0 + 8][kh + qd];
                af[mt][2] = As[r0][kh + qd + 4];
                af[mt][3] = As[r0 + 8][kh + qd + 4];
            }
#pragma unroll
            for (int nt = 0; nt < 4; nt++) {
                int n0 = wn + nt*8 + grp;
                bf[nt][0] = Bs[n0][kh + qd];
                bf[nt][1] = Bs[n0][kh + qd + 4];
            }
#pragma unroll
            for (int mt = 0; mt < 4; mt++)
#pragma unroll
                for (int nt = 0; nt < 4; nt++)
                    mma_tf32(c[mt][nt][0], c[mt][nt][1], c[mt][nt][2], c[mt][nt][3],
                             af[mt][0], af[mt][1], af[mt][2], af[mt][3],
                             bf[nt][0], bf[nt][1]);
        }
        __syncthreads();
    }

#pragma unroll
    for (int mt = 0; mt < 4; mt++) {
        int r0 = bm + wm + mt*16 + grp;
#pragma unroll
        for (int nt = 0; nt < 4; nt++) {
            int cb = bn + wn + nt*8 + 2*qd;
            float bi0 = bias[cb], bi1 = bias[cb + 1];
            float v0 = c[mt][nt][0] + bi0;
            float v1 = c[mt][nt][1] + bi1;
            float v2 = c[mt][nt][2] + bi0;
            float v3 = c[mt][nt][3] + bi1;
            if (relu) {
                v0 = fmaxf(v0, 0.f); v1 = fmaxf(v1, 0.f);
                v2 = fmaxf(v2, 0.f); v3 = fmaxf(v3, 0.f);
            }
            *(float2*)(C + (size_t)r0*N + cb)       = make_float2(v0, v1);
            *(float2*)(C + (size_t)(r0 + 8)*N + cb) = make_float2(v2, v3);
        }
    }
}

// --------- TF32 flash attention: one block per (b,h) ---------
// Ks [440][36], VT [32][444], P smem per warp [16][100]
#define ATTN_SMEM ((440*36 + 32*444 + 8*16*100)*4)
__global__ __launch_bounds__(256, 1) void k_attn(const float* __restrict__ abias)
{
    extern __shared__ float smf[];
    unsigned* Ks = (unsigned*)smf;             // [440][36]
    unsigned* VT = Ks + 440*36;                // [32][444]
    unsigned* Ps = VT + 32*444;                // 8 x [16][100]
    int b = blockIdx.x >> 3, hh = blockIdx.x & 7;
    int tid = threadIdx.x, lane = tid & 31, warp = tid >> 5;
    int grp = lane >> 2, qd = lane & 3;
    const float* qkvb = g_qkv + (size_t)b * SSEQ * 768;

    for (int idx = tid; idx < SSEQ*32; idx += 256) {
        int s = idx >> 5, d = idx & 31;
        float kv = qkvb[(size_t)s*768 + 256 + hh*32 + d];
        float vv = qkvb[(size_t)s*768 + 512 + hh*32 + d];
        Ks[s*36 + d] = f2tf(kv);
        VT[d*444 + s] = f2tf(vv);
    }
    __syncthreads();

    unsigned* Pw = Ps + warp * 16 * 100;
    const float scale = 0.17677669529663687f; // 1/sqrt(32)

    for (int mt = warp; mt < 28; mt += 8) {
        int q0 = mt * 16;
        int qr0 = q0 + grp;      if (qr0 > 439) qr0 = 439;
        int qr1 = q0 + grp + 8;  if (qr1 > 439) qr1 = 439;
        const float* Qp0 = qkvb + (size_t)qr0*768 + hh*32;
        const float* Qp1 = qkvb + (size_t)qr1*768 + hh*32;
        unsigned aq[4][4];
#pragma unroll
        for (int ks = 0; ks < 4; ks++) {
            aq[ks][0] = f2tf(Qp0[ks*8 + qd]);
            aq[ks][1] = f2tf(Qp1[ks*8 + qd]);
            aq[ks][2] = f2tf(Qp0[ks*8 + qd + 4]);
            aq[ks][3] = f2tf(Qp1[ks*8 + qd + 4]);
        }
        const float* bp0 = abias + (size_t)qr0 * SSEQ;
        const float* bp1 = abias + (size_t)qr1 * SSEQ;

        float o[4][4];
#pragma unroll
        for (int dc = 0; dc < 4; dc++)
#pragma unroll
            for (int r = 0; r < 4; r++) o[dc][r] = 0.f;
        float m0 = -1e30f, m1 = -1e30f, l0 = 0.f, l1 = 0.f;

        for (int ch = 0; ch < 5; ch++) {
            int kbase = ch * 88;
            float cs[11][4];
#pragma unroll
            for (int nc = 0; nc < 11; nc++) {
                int n0 = kbase + nc*8;
                float c0 = 0.f, c1 = 0.f, c2 = 0.f, c3 = 0.f;
                const unsigned* kr = Ks + (n0 + grp)*36;
#pragma unroll
                for (int ks = 0; ks < 4; ks++)
                    mma_tf32(c0, c1, c2, c3,
                             aq[ks][0], aq[ks][1], aq[ks][2], aq[ks][3],
                             kr[ks*8 + qd], kr[ks*8 + qd + 4]);
                float2 bb0 = *(const float2*)(bp0 + n0 + 2*qd);
                float2 bb1 = *(const float2*)(bp1 + n0 + 2*qd);
                cs[nc][0] = fmaf(c0, scale, bb0.x);
                cs[nc][1] = fmaf(c1, scale, bb0.y);
                cs[nc][2] = fmaf(c2, scale, bb1.x);
                cs[nc][3] = fmaf(c3, scale, bb1.y);
            }
            // chunk row-max
            float cm0 = -1e30f, cm1 = -1e30f;
#pragma unroll
            for (int nc = 0; nc < 11; nc++) {
                cm0 = fmaxf(cm0, fmaxf(cs[nc][0], cs[nc][1]));
                cm1 = fmaxf(cm1, fmaxf(cs[nc][2], cs[nc][3]));
            }
            cm0 = fmaxf(cm0, __shfl_xor_sync(~0u, cm0, 1));
            cm0 = fmaxf(cm0, __shfl_xor_sync(~0u, cm0, 2));
            cm1 = fmaxf(cm1, __shfl_xor_sync(~0u, cm1, 1));
            cm1 = fmaxf(cm1, __shfl_xor_sync(~0u, cm1, 2));
            float nm0 = fmaxf(m0, cm0), nm1 = fmaxf(m1, cm1);
            float f0 = __expf(m0 - nm0), f1 = __expf(m1 - nm1);
            m0 = nm0; m1 = nm1;
            l0 *= f0; l1 *= f1;
#pragma unroll
            for (int dc = 0; dc < 4; dc++) {
                o[dc][0] *= f0; o[dc][1] *= f0;
                o[dc][2] *= f1; o[dc][3] *= f1;
            }
            float ps0 = 0.f, ps1 = 0.f;
#pragma unroll
            for (int nc = 0; nc < 11; nc++) {
                float e0 = __expf(cs[nc][0] - m0);
                float e1 = __expf(cs[nc][1] - m0);
                float e2 = __expf(cs[nc][2] - m1);
                float e3 = __expf(cs[nc][3] - m1);
                ps0 += e0 + e1; ps1 += e2 + e3;
                *(uint2*)&Pw[grp*100 + nc*8 + 2*qd]       = make_uint2(f2tf(e0), f2tf(e1));
                *(uint2*)&Pw[(grp + 8)*100 + nc*8 + 2*qd] = make_uint2(f2tf(e2), f2tf(e3));
            }
            ps0 += __shfl_xor_sync(~0u, ps0, 1);
            ps0 += __shfl_xor_sync(~0u, ps0, 2);
            ps1 += __shfl_xor_sync(~0u, ps1, 1);
            ps1 += __shfl_xor_sync(~0u, ps1, 2);
            l0 += ps0; l1 += ps1;
            __syncwarp();
            // P @ V chunk
#pragma unroll
            for (int ks = 0; ks < 11; ks++) {
                unsigned ap0 = Pw[grp*100 + ks*8 + qd];
                unsigned ap1 = Pw[(grp + 8)*100 + ks*8 + qd];
                unsigned ap2 = Pw[grp*100 + ks*8 + qd + 4];
                unsigned ap3 = Pw[(grp + 8)*100 + ks*8 + qd + 4];
#pragma unroll
                for (int dc = 0; dc < 4; dc++) {
                    const unsigned* vr = VT + (dc*8 + grp)*444 + kbase + ks*8;
                    mma_tf32(o[dc][0], o[dc][1], o[dc][2], o[dc][3],
                             ap0, ap1, ap2, ap3, vr[qd], vr[qd + 4]);
                }
            }
            __syncwarp();
        }
        float inv0 = 1.f / l0, inv1 = 1.f / l1;
        int qa = q0 + grp, qb = q0 + grp + 8;
#pragma unroll
        for (int dc = 0; dc < 4; dc++) {
            int dcol = hh*32 + dc*8 + 2*qd;
            if (qa < SSEQ)
                *(float2*)(g_t1 + ((size_t)b*SSEQ + qa)*DDIM + dcol) =
                    make_float2(o[dc][0]*inv0, o[dc][1]*inv0);
            if (qb < SSEQ)
                *(float2*)(g_t1 + ((size_t)b*SSEQ + qb)*DDIM + dcol) =
                    make_float2(o[dc][2]*inv1, o[dc][3]*inv1);
        }
    }
}

// ------------- fused residual + layernorm (in place on g_h) -------------
__global__ __launch_bounds__(256) void k_ln(const float* __restrict__ add,
                                            const float* __restrict__ gam,
                                            const float* __restrict__ bet)
{
    int r = blockIdx.x, d = threadIdx.x;
    size_t i = (size_t)r*DDIM + d;
    float v = g_h[i] + add[i];
    float s1 = v, s2 = v*v;
#pragma unroll
    for (int o = 16; o > 0; o >>= 1) {
        s1 += __shfl_xor_sync(~0u, s1, o);
        s2 += __shfl_xor_sync(~0u, s2, o);
    }
    __shared__ float a1s[8], a2s[8];
    if ((d & 31) == 0) { a1s[d>>5] = s1; a2s[d>>5] = s2; }
    __syncthreads();
    float t1 = 0.f, t2 = 0.f;
#pragma unroll
    for (int j = 0; j < 8; j++) { t1 += a1s[j]; t2 += a2s[j]; }
    float m = t1 * (1.f/256.f);
    float var = t2 * (1.f/256.f) - m*m;
    g_h[i] = (v - m) * rsqrtf(var + 1e-5f) * gam[d] + bet[d];
}

// --------- fused grid-scatter + 3 dilated grouped convs + gather ---------
#define CONV_SMEM ((32*484 + 32*32*9)*4)
__global__ __launch_bounds__(256) void k_conv(
    const float* __restrict__ cw1, const float* __restrict__ cb1,
    const float* __restrict__ cw2, const float* __restrict__ cb2,
    const float* __restrict__ cw3, const float* __restrict__ cb3,
    float* __restrict__ out)
{
    extern __shared__ float sm[];
    float* sx = sm;              // [32 ch][484]
    float* sw = sm + 32*484;     // [32 oc][32 ic][9]
    int b = blockIdx.x >> 3, grp = blockIdx.x & 7;
    int tid = threadIdx.x, lane = tid & 31, warp = tid >> 5;
    const float* hb = g_h + (size_t)b * SSEQ * DDIM;

    for (int p = warp; p < 484; p += 8) {
        float v = (p < SSEQ) ? hb[(size_t)p*DDIM + grp*32 + lane] : 0.f;
        sx[lane*484 + p] = v;
    }

    int ocb = warp * 4;
    float tot[7][2][4];
#pragma unroll
    for (int it = 0; it < 7; it++)
#pragma unroll
        for (int pr = 0; pr < 2; pr++)
#pragma unroll
            for (int j = 0; j < 4; j++) tot[it][pr][j] = 0.f;

    const float* cws[3] = {cw1, cw2, cw3};
    const float* cbs[3] = {cb1, cb2, cb3};

    for (int cv = 0; cv < 3; cv++) {
        int dil = cv + 1;
        __syncthreads();
        const float* src = cws[cv] + (size_t)grp * 32 * 288;
        for (int i = tid; i < 32*288; i += 256) sw[i] = src[i];
        __syncthreads();
        float cbv[4];
#pragma unroll
        for (int j = 0; j < 4; j++) cbv[j] = cbs[cv][grp*32 + ocb + j];

#pragma unroll
        for (int it = 0; it < 7; it++) {
            int pxA = lane + 32*it;
            int pxB = pxA + 224;
            int rA = pxA / 22, cA = pxA % 22;
            int rB = pxB / 22, cB = pxB % 22;
            int offA[9], offB[9];
            int t = 0;
#pragma unroll
            for (int dr = -1; dr <= 1; dr++)
#pragma unroll
                for (int dc = -1; dc <= 1; dc++) {
                    int ri = rA + dil*dr, ci = cA + dil*dc;
                    offA[t] = (ri >= 0 && ri < 22 && ci >= 0 && ci < 22) ? ri*22 + ci : -1;
                    ri = rB + dil*dr; ci = cB + dil*dc;
                    offB[t] = (pxB < SSEQ && ri >= 0 && ri < 22 && ci >= 0 && ci < 22) ? ri*22 + ci : -1;
                    t++;
                }
            float accA[4] = {0.f, 0.f, 0.f, 0.f};
            float accB[4] = {0.f, 0.f, 0.f, 0.f};
            for (int ic = 0; ic < 32; ic++) {
                const float* xb = sx + ic*484;
                float xvA[9], xvB[9];
#pragma unroll
                for (int tt = 0; tt < 9; tt++) {
                    xvA[tt] = (offA[tt] >= 0) ? xb[offA[tt]] : 0.f;
                    xvB[tt] = (offB[tt] >= 0) ? xb[offB[tt]] : 0.f;
                }
#pragma unroll
                for (int j = 0; j < 4; j++) {
                    const float* wj = sw + (ocb + j)*288 + ic*9;
#pragma unroll
                    for (int tt = 0; tt < 9; tt++) {
                        float w = wj[tt];
                        accA[j] = fmaf(w, xvA[tt], accA[j]);
                        accB[j] = fmaf(w, xvB[tt], accB[j]);
                    }
                }
            }
#pragma unroll
            for (int j = 0; j < 4; j++) {
                tot[it][0][j] += fmaxf(accA[j] + cbv[j], 0.f);
                tot[it][1][j] += fmaxf(accB[j] + cbv[j], 0.f);
            }
        }
    }

    float* ob = out + (size_t)b * SSEQ * DDIM;
#pragma unroll
    for (int it = 0; it < 7; it++) {
#pragma unroll
        for (int pr = 0; pr < 2; pr++) {
            int px = lane + 32*it + 224*pr;
            if (px < SSEQ) {
#pragma unroll
                for (int j = 0; j < 4; j++) {
                    int oc = ocb + j;
                    ob[(size_t)px*DDIM + grp*32 + oc] =
                        0.5f * (sx[oc*484 + px] + tot[it][pr][j]);
                }
            }
        }
    }
}

// ------------------------------ launcher ------------------------------
extern "C" void kernel_launch(void* const* d_in, const int* in_sizes, int n_in,
                              void* d_out, int out_size)
{
    const int* x    = (const int*)d_in[0];
    const float* ev   = (const float*)d_in[2];
    const float* px   = (const float*)d_in[3];
    const float* py   = (const float*)d_in[4];
    const float* st   = (const float*)d_in[5];
    const int* tkx = (const int*)d_in[6];
    const int* tky = (const int*)d_in[7];
    const int* tks = (const int*)d_in[8];
    const float* abias = (const float*)d_in[9];
    const float* Wqkv = (const float*)d_in[10];
    const float* bqkv = (const float*)d_in[11];
    const float* Wo   = (const float*)d_in[12];
    const float* bo   = (const float*)d_in[13];
    const float* W1   = (const float*)d_in[14];
    const float* b1   = (const float*)d_in[15];
    const float* W2   = (const float*)d_in[16];
    const float* b2   = (const float*)d_in[17];
    const float* ln1s = (const float*)d_in[18];
    const float* ln1b = (const float*)d_in[19];
    const float* ln2s = (const float*)d_in[20];
    const float* ln2b = (const float*)d_in[21];
    const float* cw1  = (const float*)d_in[22];
    const float* cb1  = (const float*)d_in[23];
    const float* cw2  = (const float*)d_in[24];
    const float* cb2  = (const float*)d_in[25];
    const float* cw3  = (const float*)d_in[26];
    const float* cb3  = (const float*)d_in[27];
    float* out = (float*)d_out;

    float *hP, *qkvP, *t1P, *t2P;
    cudaGetSymbolAddress((void**)&hP,   g_h);
    cudaGetSymbolAddress((void**)&qkvP, g_qkv);
    cudaGetSymbolAddress((void**)&t1P,  g_t1);
    cudaGetSymbolAddress((void**)&t2P,  g_t2);

    cudaFuncSetAttribute(k_attn, cudaFuncAttributeMaxDynamicSharedMemorySize, ATTN_SMEM);
    cudaFuncSetAttribute(k_conv, cudaFuncAttributeMaxDynamicSharedMemorySize, CONV_SMEM);

    k_embed<<<BS_, 256>>>(x, ev, px, py, st, tkx, tky, tks);

    for (int l = 0; l < LNUM; l++) {
        k_gemm<<<dim3(6, 220), 256>>>(hP, Wqkv + (size_t)l*768*256, bqkv + l*768,
                                      qkvP, BS_, 768, 256, 0);
        k_attn<<<BB*HN, 256, ATTN_SMEM>>>(abias);
        k_gemm<<<dim3(2, 220), 256>>>(t1P, Wo + (size_t)l*256*256, bo + l*256,
                                      t2P, BS_, 256, 256, 0);
        k_ln<<<BS_, 256>>>(t2P, ln1s + l*256, ln1b + l*256);
        k_gemm<<<dim3(4, 220), 256>>>(hP, W1 + (size_t)l*512*256, b1 + l*512,
                                      t1P, BS_, 512, 256, 1);
        k_gemm<<<dim3(2, 220), 256>>>(t1P, W2 + (size_t)l*256*512, b2 + l*256,
                                      t2P, BS_, 256, 512, 0);
        k_ln<<<BS_, 256>>>(t2P, ln2s + l*256, ln2b + l*256);
        float* cout = (l == LNUM-1) ? out : hP;
        k_conv<<<BB*HN, 256, CONV_SMEM>>>(cw1 + (size_t)l*256*288, cb1 + l*256,
                                          cw2 + (size_t)l*256*288, cb2 + l*256,
                                          cw3 + (size_t)l*256*288, cb3 + l*256,
                                          cout);
    }
}

// round 8
// speedup vs baseline: 3.0704x; 2.0208x over previous
#include <cuda_runtime.h>
#include <cuda_bf16.h>

#define BB 64
#define SSEQ 440
#define DDIM 256
#define HN 8
#define FFD 512
#define LNUM 6
#define BS_ (BB*SSEQ)   // 28160

// ------------ static device scratch (no allocation) ------------
__device__ float g_h[(size_t)BS_*DDIM];
__device__ float g_qkv[(size_t)BS_*3*DDIM];
__device__ float g_t1[(size_t)BS_*FFD];
__device__ float g_t2[(size_t)BS_*DDIM];

__device__ __forceinline__ unsigned f2tf(float f) {
    unsigned u;
    asm("cvt.rna.tf32.f32 %0, %1;" : "=r"(u) : "f"(f));
    return u;
}

__device__ __forceinline__ void mma_tf32(float& c0, float& c1, float& c2, float& c3,
                                         unsigned a0, unsigned a1, unsigned a2, unsigned a3,
                                         unsigned b0, unsigned b1)
{
    asm volatile(
        "mma.sync.aligned.m16n8k8.row.col.f32.tf32.tf32.f32 "
        "{%0,%1,%2,%3}, {%4,%5,%6,%7}, {%8,%9}, {%0,%1,%2,%3};"
        : "+f"(c0), "+f"(c1), "+f"(c2), "+f"(c3)
        : "r"(a0), "r"(a1), "r"(a2), "r"(a3), "r"(b0), "r"(b1));
}

// ------------------------ embedding ------------------------
__global__ void k_embed(const int* __restrict__ x,
                        const float* __restrict__ ev, const float* __restrict__ px,
                        const float* __restrict__ py, const float* __restrict__ st,
                        const int* __restrict__ tkx, const int* __restrict__ tky,
                        const int* __restrict__ tks)
{
    int bs = blockIdx.x;
    int s = bs % SSEQ;
    int d = threadIdx.x;
    int xi = x[bs];
    g_h[(size_t)bs*DDIM + d] =
        ev[xi*DDIM + d] + px[tkx[s]*DDIM + d] + py[tky[s]*DDIM + d] + st[tks[s]*DDIM + d];
}

// ---- TF32 tensor-core GEMM: C[M,N] = A[M,K] @ W[N,K]^T + bias (opt relu) ----
__global__ __launch_bounds__(256, 2) void k_gemm(
    const float* __restrict__ A, const float* __restrict__ W,
    const float* __restrict__ bias, float* __restrict__ C,
    int M, int N, int K, int relu)
{
    __shared__ unsigned As[128][20];
    __shared__ unsigned Bs[128][20];
    int tid = threadIdx.x;
    int bm = blockIdx.y * 128, bn = blockIdx.x * 128;
    int row = tid >> 1, kq = (tid & 1) * 8;
    const float* Ap = A + (size_t)(bm + row) * K + kq;
    const float* Wp = W + (size_t)(bn + row) * K + kq;
    float4 pa0 = *(const float4*)Ap;
    float4 pa1 = *(const float4*)(Ap + 4);
    float4 pb0 = *(const float4*)Wp;
    float4 pb1 = *(const float4*)(Wp + 4);

    int lane = tid & 31, warp = tid >> 5;
    int wm = (warp & 1) * 64, wn = (warp >> 1) * 32;
    int grp = lane >> 2, qd = lane & 3;

    float c[4][4][4];
#pragma unroll
    for (int mt = 0; mt < 4; mt++)
#pragma unroll
        for (int nt = 0; nt < 4; nt++)
#pragma unroll
            for (int r = 0; r < 4; r++) c[mt][nt][r] = 0.f;

    int nk = K >> 4;
    for (int kt = 0; kt < nk; kt++) {
        *(uint4*)&As[row][kq]     = make_uint4(f2tf(pa0.x), f2tf(pa0.y), f2tf(pa0.z), f2tf(pa0.w));
        *(uint4*)&As[row][kq + 4] = make_uint4(f2tf(pa1.x), f2tf(pa1.y), f2tf(pa1.z), f2tf(pa1.w));
        *(uint4*)&Bs[row][kq]     = make_uint4(f2tf(pb0.x), f2tf(pb0.y), f2tf(pb0.z), f2tf(pb0.w));
        *(uint4*)&Bs[row][kq + 4] = make_uint4(f2tf(pb1.x), f2tf(pb1.y), f2tf(pb1.z), f2tf(pb1.w));
        __syncthreads();
        if (kt + 1 < nk) {
            const float* Ap2 = Ap + (size_t)(kt + 1) * 16;
            const float* Wp2 = Wp + (size_t)(kt + 1) * 16;
            pa0 = *(const float4*)Ap2; pa1 = *(const float4*)(Ap2 + 4);
            pb0 = *(const float4*)Wp2; pb1 = *(const float4*)(Wp2 + 4);
        }
#pragma unroll
        for (int kh = 0; kh < 16; kh += 8) {
            unsigned af[4][4], bf[4][2];
#pragma unroll
            for (int mt = 0; mt < 4; mt++) {
                int r0 = wm + mt*16 + grp;
                af[mt][0] = As[r0][kh + qd];
                af[mt][1] = As[r0 + 8][kh + qd];
                af[mt][2] = As[r0][kh + qd + 4];
                af[mt][3] = As[r0 + 8][kh + qd + 4];
            }
#pragma unroll
            for (int nt = 0; nt < 4; nt++) {
                int n0 = wn + nt*8 + grp;
                bf[nt][0] = Bs[n0][kh + qd];
                bf[nt][1] = Bs[n0][kh + qd + 4];
            }
#pragma unroll
            for (int mt = 0; mt < 4; mt++)
#pragma unroll
                for (int nt = 0; nt < 4; nt++)
                    mma_tf32(c[mt][nt][0], c[mt][nt][1], c[mt][nt][2], c[mt][nt][3],
                             af[mt][0], af[mt][1], af[mt][2], af[mt][3],
                             bf[nt][0], bf[nt][1]);
        }
        __syncthreads();
    }

#pragma unroll
    for (int mt = 0; mt < 4; mt++) {
        int r0 = bm + wm + mt*16 + grp;
#pragma unroll
        for (int nt = 0; nt < 4; nt++) {
            int cb = bn + wn + nt*8 + 2*qd;
            float bi0 = bias[cb], bi1 = bias[cb + 1];
            float v0 = c[mt][nt][0] + bi0;
            float v1 = c[mt][nt][1] + bi1;
            float v2 = c[mt][nt][2] + bi0;
            float v3 = c[mt][nt][3] + bi1;
            if (relu) {
                v0 = fmaxf(v0, 0.f); v1 = fmaxf(v1, 0.f);
                v2 = fmaxf(v2, 0.f); v3 = fmaxf(v3, 0.f);
            }
            *(float2*)(C + (size_t)r0*N + cb)       = make_float2(v0, v1);
            *(float2*)(C + (size_t)(r0 + 8)*N + cb) = make_float2(v2, v3);
        }
    }
}

// --------- TF32 flash attention: one block per (b,h) ---------
#define ATTN_SMEM ((440*36 + 32*444 + 8*16*100)*4)
__global__ __launch_bounds__(256, 1) void k_attn(const float* __restrict__ abias)
{
    extern __shared__ float smf[];
    unsigned* Ks = (unsigned*)smf;             // [440][36]
    unsigned* VT = Ks + 440*36;                // [32][444]
    unsigned* Ps = VT + 32*444;                // 8 x [16][100]
    int b = blockIdx.x >> 3, hh = blockIdx.x & 7;
    int tid = threadIdx.x, lane = tid & 31, warp = tid >> 5;
    int grp = lane >> 2, qd = lane & 3;
    const float* qkvb = g_qkv + (size_t)b * SSEQ * 768;

    for (int idx = tid; idx < SSEQ*32; idx += 256) {
        int s = idx >> 5, d = idx & 31;
        float kv = qkvb[(size_t)s*768 + 256 + hh*32 + d];
        float vv = qkvb[(size_t)s*768 + 512 + hh*32 + d];
        Ks[s*36 + d] = f2tf(kv);
        VT[d*444 + s] = f2tf(vv);
    }
    __syncthreads();

    unsigned* Pw = Ps + warp * 16 * 100;
    const float scale = 0.17677669529663687f;

    for (int mt = warp; mt < 28; mt += 8) {
        int q0 = mt * 16;
        int qr0 = q0 + grp;      if (qr0 > 439) qr0 = 439;
        int qr1 = q0 + grp + 8;  if (qr1 > 439) qr1 = 439;
        const float* Qp0 = qkvb + (size_t)qr0*768 + hh*32;
        const float* Qp1 = qkvb + (size_t)qr1*768 + hh*32;
        unsigned aq[4][4];
#pragma unroll
        for (int ks = 0; ks < 4; ks++) {
            aq[ks][0] = f2tf(Qp0[ks*8 + qd]);
            aq[ks][1] = f2tf(Qp1[ks*8 + qd]);
            aq[ks][2] = f2tf(Qp0[ks*8 + qd + 4]);
            aq[ks][3] = f2tf(Qp1[ks*8 + qd + 4]);
        }
        const float* bp0 = abias + (size_t)qr0 * SSEQ;
        const float* bp1 = abias + (size_t)qr1 * SSEQ;

        float o[4][4];
#pragma unroll
        for (int dc = 0; dc < 4; dc++)
#pragma unroll
            for (int r = 0; r < 4; r++) o[dc][r] = 0.f;
        float m0 = -1e30f, m1 = -1e30f, l0 = 0.f, l1 = 0.f;

        for (int ch = 0; ch < 5; ch++) {
            int kbase = ch * 88;
            float cs[11][4];
#pragma unroll
            for (int nc = 0; nc < 11; nc++) {
                int n0 = kbase + nc*8;
                float c0 = 0.f, c1 = 0.f, c2 = 0.f, c3 = 0.f;
                const unsigned* kr = Ks + (n0 + grp)*36;
#pragma unroll
                for (int ks = 0; ks < 4; ks++)
                    mma_tf32(c0, c1, c2, c3,
                             aq[ks][0], aq[ks][1], aq[ks][2], aq[ks][3],
                             kr[ks*8 + qd], kr[ks*8 + qd + 4]);
                float2 bb0 = *(const float2*)(bp0 + n0 + 2*qd);
                float2 bb1 = *(const float2*)(bp1 + n0 + 2*qd);
                cs[nc][0] = fmaf(c0, scale, bb0.x);
                cs[nc][1] = fmaf(c1, scale, bb0.y);
                cs[nc][2] = fmaf(c2, scale, bb1.x);
                cs[nc][3] = fmaf(c3, scale, bb1.y);
            }
            float cm0 = -1e30f, cm1 = -1e30f;
#pragma unroll
            for (int nc = 0; nc < 11; nc++) {
                cm0 = fmaxf(cm0, fmaxf(cs[nc][0], cs[nc][1]));
                cm1 = fmaxf(cm1, fmaxf(cs[nc][2], cs[nc][3]));
            }
            cm0 = fmaxf(cm0, __shfl_xor_sync(~0u, cm0, 1));
            cm0 = fmaxf(cm0, __shfl_xor_sync(~0u, cm0, 2));
            cm1 = fmaxf(cm1, __shfl_xor_sync(~0u, cm1, 1));
            cm1 = fmaxf(cm1, __shfl_xor_sync(~0u, cm1, 2));
            float nm0 = fmaxf(m0, cm0), nm1 = fmaxf(m1, cm1);
            float f0 = __expf(m0 - nm0), f1 = __expf(m1 - nm1);
            m0 = nm0; m1 = nm1;
            l0 *= f0; l1 *= f1;
#pragma unroll
            for (int dc = 0; dc < 4; dc++) {
                o[dc][0] *= f0; o[dc][1] *= f0;
                o[dc][2] *= f1; o[dc][3] *= f1;
            }
            float ps0 = 0.f, ps1 = 0.f;
#pragma unroll
            for (int nc = 0; nc < 11; nc++) {
                float e0 = __expf(cs[nc][0] - m0);
                float e1 = __expf(cs[nc][1] - m0);
                float e2 = __expf(cs[nc][2] - m1);
                float e3 = __expf(cs[nc][3] - m1);
                ps0 += e0 + e1; ps1 += e2 + e3;
                *(uint2*)&Pw[grp*100 + nc*8 + 2*qd]       = make_uint2(f2tf(e0), f2tf(e1));
                *(uint2*)&Pw[(grp + 8)*100 + nc*8 + 2*qd] = make_uint2(f2tf(e2), f2tf(e3));
            }
            ps0 += __shfl_xor_sync(~0u, ps0, 1);
            ps0 += __shfl_xor_sync(~0u, ps0, 2);
            ps1 += __shfl_xor_sync(~0u, ps1, 1);
            ps1 += __shfl_xor_sync(~0u, ps1, 2);
            l0 += ps0; l1 += ps1;
            __syncwarp();
#pragma unroll
            for (int ks = 0; ks < 11; ks++) {
                unsigned ap0 = Pw[grp*100 + ks*8 + qd];
                unsigned ap1 = Pw[(grp + 8)*100 + ks*8 + qd];
                unsigned ap2 = Pw[grp*100 + ks*8 + qd + 4];
                unsigned ap3 = Pw[(grp + 8)*100 + ks*8 + qd + 4];
#pragma unroll
                for (int dc = 0; dc < 4; dc++) {
                    const unsigned* vr = VT + (dc*8 + grp)*444 + kbase + ks*8;
                    mma_tf32(o[dc][0], o[dc][1], o[dc][2], o[dc][3],
                             ap0, ap1, ap2, ap3, vr[qd], vr[qd + 4]);
                }
            }
            __syncwarp();
        }
        float inv0 = 1.f / l0, inv1 = 1.f / l1;
        int qa = q0 + grp, qb = q0 + grp + 8;
#pragma unroll
        for (int dc = 0; dc < 4; dc++) {
            int dcol = hh*32 + dc*8 + 2*qd;
            if (qa < SSEQ)
                *(float2*)(g_t1 + ((size_t)b*SSEQ + qa)*DDIM + dcol) =
                    make_float2(o[dc][0]*inv0, o[dc][1]*inv0);
            if (qb < SSEQ)
                *(float2*)(g_t1 + ((size_t)b*SSEQ + qb)*DDIM + dcol) =
                    make_float2(o[dc][2]*inv1, o[dc][3]*inv1);
        }
    }
}

// ------------- fused residual + layernorm (in place on g_h) -------------
__global__ __launch_bounds__(256) void k_ln(const float* __restrict__ add,
                                            const float* __restrict__ gam,
                                            const float* __restrict__ bet)
{
    int r = blockIdx.x, d = threadIdx.x;
    size_t i = (size_t)r*DDIM + d;
    float v = g_h[i] + add[i];
    float s1 = v, s2 = v*v;
#pragma unroll
    for (int o = 16; o > 0; o >>= 1) {
        s1 += __shfl_xor_sync(~0u, s1, o);
        s2 += __shfl_xor_sync(~0u, s2, o);
    }
    __shared__ float a1s[8], a2s[8];
    if ((d & 31) == 0) { a1s[d>>5] = s1; a2s[d>>5] = s2; }
    __syncthreads();
    float t1 = 0.f, t2 = 0.f;
#pragma unroll
    for (int j = 0; j < 8; j++) { t1 += a1s[j]; t2 += a2s[j]; }
    float m = t1 * (1.f/256.f);
    float var = t2 * (1.f/256.f) - m*m;
    g_h[i] = (v - m) * rsqrtf(var + 1e-5f) * gam[d] + bet[d];
}

// --------- TF32 mma conv: canvas implicit GEMM, one block per (b, group) ---------
// canvas [32ic][28x28 halo grid] stride 808 (=8 mod 32), weights [9 taps][32oc][stride 36]
#define CVST 808
#define WST  36
#define CONV_SMEM ((32*CVST + 9*32*WST)*4)
__global__ __launch_bounds__(256, 1) void k_conv(
    const float* __restrict__ cw1, const float* __restrict__ cb1,
    const float* __restrict__ cw2, const float* __restrict__ cb2,
    const float* __restrict__ cw3, const float* __restrict__ cb3,
    float* __restrict__ out)
{
    extern __shared__ unsigned usm[];
    unsigned* cx  = usm;                 // [32][CVST], canvas 28x28 per ic (tf32 bits)
    unsigned* swt = usm + 32*CVST;       // [9][32][WST] (tf32 bits)
    int b = blockIdx.x >> 3, gch = blockIdx.x & 7;
    int tid = threadIdx.x, lane = tid & 31, warp = tid >> 5;
    int grp = lane >> 2, qd = lane & 3;
    const float* hb = g_h + (size_t)b * SSEQ * DDIM;

    for (int i = tid; i < 32*CVST; i += 256) cx[i] = 0u;
    __syncthreads();
    // fill canvas: px -> canvas idx = px + 6*(px/22) + 3*28+3
    for (int idx = tid; idx < SSEQ*32; idx += 256) {
        int p = idx >> 5, c = idx & 31;
        int cidx = p + 6*(p/22) + 87;
        cx[c*CVST + cidx] = f2tf(hb[(size_t)p*DDIM + gch*32 + c]);
    }

    const float* cws[3] = {cw1, cw2, cw3};
    const float* cbs[3] = {cb1, cb2, cb3};

    int mt0 = warp;   // tiles {warp, warp+8}, then {warp+16, warp+24}
#pragma unroll
    for (int half = 0; half < 2; half++) {
        int tA = mt0 + 16*half;          // tile A, tile B = tA+8
        int pxA0 = tA*16 + grp;          // c-rows grp / grp+8 of tile A
        int pxA1 = pxA0 + 8;
        int pxB0 = (tA + 8)*16 + grp;
        int pxB1 = pxB0 + 8;
        int ciA0 = pxA0 + 6*(pxA0/22) + 87;
        int ciA1 = pxA1 + 6*(pxA1/22) + 87;
        int ciB0 = pxB0 + 6*(pxB0/22) + 87;
        int ciB1 = pxB1 + 6*(pxB1/22) + 87;

        float tot[2][4][4];
#pragma unroll
        for (int p = 0; p < 2; p++)
#pragma unroll
            for (int nt = 0; nt < 4; nt++)
#pragma unroll
                for (int r = 0; r < 4; r++) tot[p][nt][r] = 0.f;

        for (int cv = 0; cv < 3; cv++) {
            int dil = cv + 1;
            // stage weights for this conv: [oc][ic][t] -> swt[t][oc][ic]
            __syncthreads();
            const float* src = cws[cv] + (size_t)gch * 32 * 288;
            for (int i = tid; i < 32*288; i += 256) {
                int oc = i / 288, rem = i - oc*288;
                int ic = rem / 9, t = rem - ic*9;
                swt[t*32*WST + oc*WST + ic] = f2tf(src[i]);
            }
            __syncthreads();

            float acc[2][4][4];
#pragma unroll
            for (int p = 0; p < 2; p++)
#pragma unroll
                for (int nt = 0; nt < 4; nt++)
#pragma unroll
                    for (int r = 0; r < 4; r++) acc[p][nt][r] = 0.f;

            for (int t = 0; t < 9; t++) {
                int sh = (t/3 - 1)*dil*28 + (t%3 - 1)*dil;
                const unsigned* wt = swt + t*32*WST;
#pragma unroll
                for (int ks = 0; ks < 4; ks++) {
                    int ic0 = ks*8 + qd;
                    const unsigned* r0 = cx + ic0*CVST + sh;
                    const unsigned* r1 = cx + (ic0 + 4)*CVST + sh;
                    unsigned aA0 = r0[ciA0], aA1 = r0[ciA1];
                    unsigned aA2 = r1[ciA0], aA3 = r1[ciA1];
                    unsigned aB0 = r0[ciB0], aB1 = r0[ciB1];
                    unsigned aB2 = r1[ciB0], aB3 = r1[ciB1];
#pragma unroll
                    for (int nt = 0; nt < 4; nt++) {
                        unsigned b0 = wt[(nt*8 + grp)*WST + ic0];
                        unsigned b1 = wt[(nt*8 + grp)*WST + ic0 + 4];
                        mma_tf32(acc[0][nt][0], acc[0][nt][1], acc[0][nt][2], acc[0][nt][3],
                                 aA0, aA1, aA2, aA3, b0, b1);
                        mma_tf32(acc[1][nt][0], acc[1][nt][1], acc[1][nt][2], acc[1][nt][3],
                                 aB0, aB1, aB2, aB3, b0, b1);
                    }
                }
            }
            // bias + relu -> tot
#pragma unroll
            for (int nt = 0; nt < 4; nt++) {
                float bi0 = cbs[cv][gch*32 + nt*8 + 2*qd];
                float bi1 = cbs[cv][gch*32 + nt*8 + 2*qd + 1];
#pragma unroll
                for (int p = 0; p < 2; p++) {
                    tot[p][nt][0] += fmaxf(acc[p][nt][0] + bi0, 0.f);
                    tot[p][nt][1] += fmaxf(acc[p][nt][1] + bi1, 0.f);
                    tot[p][nt][2] += fmaxf(acc[p][nt][2] + bi0, 0.f);
                    tot[p][nt][3] += fmaxf(acc[p][nt][3] + bi1, 0.f);
                }
            }
        }

        // store: out = 0.5*(h + sum convs); residual read from gmem (exact)
        float* ob = out + (size_t)b * SSEQ * DDIM;
#pragma unroll
        for (int p = 0; p < 2; p++) {
            int px0 = (tA + 8*p)*16 + grp;
            int px1 = px0 + 8;
#pragma unroll
            for (int nt = 0; nt < 4; nt++) {
                int ch = gch*32 + nt*8 + 2*qd;
                if (px0 < SSEQ) {
                    float r0 = hb[(size_t)px0*DDIM + ch];
                    float r1 = hb[(size_t)px0*DDIM + ch + 1];
                    *(float2*)(ob + (size_t)px0*DDIM + ch) =
                        make_float2(0.5f*(r0 + tot[p][nt][0]), 0.5f*(r1 + tot[p][nt][1]));
                }
                if (px1 < SSEQ) {
                    float r2 = hb[(size_t)px1*DDIM + ch];
                    float r3 = hb[(size_t)px1*DDIM + ch + 1];
                    *(float2*)(ob + (size_t)px1*DDIM + ch) =
                        make_float2(0.5f*(r2 + tot[p][nt][2]), 0.5f*(r3 + tot[p][nt][3]));
                }
            }
        }
        __syncthreads();
    }
}

// ------------------------------ launcher ------------------------------
extern "C" void kernel_launch(void* const* d_in, const int* in_sizes, int n_in,
                              void* d_out, int out_size)
{
    const int* x    = (const int*)d_in[0];
    const float* ev   = (const float*)d_in[2];
    const float* px   = (const float*)d_in[3];
    const float* py   = (const float*)d_in[4];
    const float* st   = (const float*)d_in[5];
    const int* tkx = (const int*)d_in[6];
    const int* tky = (const int*)d_in[7];
    const int* tks = (const int*)d_in[8];
    const float* abias = (const float*)d_in[9];
    const float* Wqkv = (const float*)d_in[10];
    const float* bqkv = (const float*)d_in[11];
    const float* Wo   = (const float*)d_in[12];
    const float* bo   = (const float*)d_in[13];
    const float* W1   = (const float*)d_in[14];
    const float* b1   = (const float*)d_in[15];
    const float* W2   = (const float*)d_in[16];
    const float* b2   = (const float*)d_in[17];
    const float* ln1s = (const float*)d_in[18];
    const float* ln1b = (const float*)d_in[19];
    const float* ln2s = (const float*)d_in[20];
    const float* ln2b = (const float*)d_in[21];
    const float* cw1  = (const float*)d_in[22];
    const float* cb1  = (const float*)d_in[23];
    const float* cw2  = (const float*)d_in[24];
    const float* cb2  = (const float*)d_in[25];
    const float* cw3  = (const float*)d_in[26];
    const float* cb3  = (const float*)d_in[27];
    float* out = (float*)d_out;

    float *hP, *qkvP, *t1P, *t2P;
    cudaGetSymbolAddress((void**)&hP,   g_h);
    cudaGetSymbolAddress((void**)&qkvP, g_qkv);
    cudaGetSymbolAddress((void**)&t1P,  g_t1);
    cudaGetSymbolAddress((void**)&t2P,  g_t2);

    cudaFuncSetAttribute(k_attn, cudaFuncAttributeMaxDynamicSharedMemorySize, ATTN_SMEM);
    cudaFuncSetAttribute(k_conv, cudaFuncAttributeMaxDynamicSharedMemorySize, CONV_SMEM);

    k_embed<<<BS_, 256>>>(x, ev, px, py, st, tkx, tky, tks);

    for (int l = 0; l < LNUM; l++) {
        k_gemm<<<dim3(6, 220), 256>>>(hP, Wqkv + (size_t)l*768*256, bqkv + l*768,
                                      qkvP, BS_, 768, 256, 0);
        k_attn<<<BB*HN, 256, ATTN_SMEM>>>(abias);
        k_gemm<<<dim3(2, 220), 256>>>(t1P, Wo + (size_t)l*256*256, bo + l*256,
                                      t2P, BS_, 256, 256, 0);
        k_ln<<<BS_, 256>>>(t2P, ln1s + l*256, ln1b + l*256);
        k_gemm<<<dim3(4, 220), 256>>>(hP, W1 + (size_t)l*512*256, b1 + l*512,
                                      t1P, BS_, 512, 256, 1);
        k_gemm<<<dim3(2, 220), 256>>>(t1P, W2 + (size_t)l*256*512, b2 + l*256,
                                      t2P, BS_, 256, 512, 0);
        k_ln<<<BS_, 256>>>(t2P, ln2s + l*256, ln2b + l*256);
        float* cout = (l == LNUM-1) ? out : hP;
        k_conv<<<BB*HN, 256, CONV_SMEM>>>(cw1 + (size_t)l*256*288, cb1 + l*256,
                                          cw2 + (size_t)l*256*288, cb2 + l*256,
                                          cw3 + (size_t)l*256*288, cb3 + l*256,
                                          cout);
    }
}

// round 9
// speedup vs baseline: 3.4846x; 1.1349x over previous
#include <cuda_runtime.h>
#include <cuda_bf16.h>
#include <cuda_fp16.h>

#define BB 64
#define SSEQ 440
#define DDIM 256
#define HN 8
#define FFD 512
#define LNUM 6
#define BS_ (BB*SSEQ)   // 28160

// ------------ static device scratch (no allocation) ------------
__device__ float g_h[(size_t)BS_*DDIM];
__device__ float g_qkv[(size_t)BS_*3*DDIM];
__device__ float g_t1[(size_t)BS_*FFD];
__device__ float g_t2[(size_t)BS_*DDIM];

__device__ __forceinline__ unsigned f2tf(float f) {
    unsigned u;
    asm("cvt.rna.tf32.f32 %0, %1;" : "=r"(u) : "f"(f));
    return u;
}

__device__ __forceinline__ void mma_tf32(float& c0, float& c1, float& c2, float& c3,
                                         unsigned a0, unsigned a1, unsigned a2, unsigned a3,
                                         unsigned b0, unsigned b1)
{
    asm volatile(
        "mma.sync.aligned.m16n8k8.row.col.f32.tf32.tf32.f32 "
        "{%0,%1,%2,%3}, {%4,%5,%6,%7}, {%8,%9}, {%0,%1,%2,%3};"
        : "+f"(c0), "+f"(c1), "+f"(c2), "+f"(c3)
        : "r"(a0), "r"(a1), "r"(a2), "r"(a3), "r"(b0), "r"(b1));
}

__device__ __forceinline__ void mma_f16_k16(float& c0, float& c1, float& c2, float& c3,
                                            unsigned a0, unsigned a1, unsigned a2, unsigned a3,
                                            unsigned b0, unsigned b1)
{
    asm volatile(
        "mma.sync.aligned.m16n8k16.row.col.f32.f16.f16.f32 "
        "{%0,%1,%2,%3}, {%4,%5,%6,%7}, {%8,%9}, {%0,%1,%2,%3};"
        : "+f"(c0), "+f"(c1), "+f"(c2), "+f"(c3)
        : "r"(a0), "r"(a1), "r"(a2), "r"(a3), "r"(b0), "r"(b1));
}

__device__ __forceinline__ void mma_f16_k8(float& c0, float& c1, float& c2, float& c3,
                                           unsigned a0, unsigned a1, unsigned b0)
{
    asm volatile(
        "mma.sync.aligned.m16n8k8.row.col.f32.f16.f16.f32 "
        "{%0,%1,%2,%3}, {%4,%5}, {%6}, {%0,%1,%2,%3};"
        : "+f"(c0), "+f"(c1), "+f"(c2), "+f"(c3)
        : "r"(a0), "r"(a1), "r"(b0));
}

__device__ __forceinline__ unsigned packh2(float a, float b) {
    __half2 h = __floats2half2_rn(a, b);
    return *(unsigned*)&h;
}

// ------------------------ embedding ------------------------
__global__ void k_embed(const int* __restrict__ x,
                        const float* __restrict__ ev, const float* __restrict__ px,
                        const float* __restrict__ py, const float* __restrict__ st,
                        const int* __restrict__ tkx, const int* __restrict__ tky,
                        const int* __restrict__ tks)
{
    int bs = blockIdx.x;
    int s = bs % SSEQ;
    int d = threadIdx.x;
    int xi = x[bs];
    g_h[(size_t)bs*DDIM + d] =
        ev[xi*DDIM + d] + px[tkx[s]*DDIM + d] + py[tky[s]*DDIM + d] + st[tks[s]*DDIM + d];
}

// ---- TF32 tensor-core GEMM: C[M,N] = A[M,K] @ W[N,K]^T + bias (opt relu) ----
__global__ __launch_bounds__(256, 2) void k_gemm(
    const float* __restrict__ A, const float* __restrict__ W,
    const float* __restrict__ bias, float* __restrict__ C,
    int M, int N, int K, int relu)
{
    __shared__ unsigned As[128][20];
    __shared__ unsigned Bs[128][20];
    int tid = threadIdx.x;
    int bm = blockIdx.y * 128, bn = blockIdx.x * 128;
    int row = tid >> 1, kq = (tid & 1) * 8;
    const float* Ap = A + (size_t)(bm + row) * K + kq;
    const float* Wp = W + (size_t)(bn + row) * K + kq;
    float4 pa0 = *(const float4*)Ap;
    float4 pa1 = *(const float4*)(Ap + 4);
    float4 pb0 = *(const float4*)Wp;
    float4 pb1 = *(const float4*)(Wp + 4);

    int lane = tid & 31, warp = tid >> 5;
    int wm = (warp & 1) * 64, wn = (warp >> 1) * 32;
    int grp = lane >> 2, qd = lane & 3;

    float c[4][4][4];
#pragma unroll
    for (int mt = 0; mt < 4; mt++)
#pragma unroll
        for (int nt = 0; nt < 4; nt++)
#pragma unroll
            for (int r = 0; r < 4; r++) c[mt][nt][r] = 0.f;

    int nk = K >> 4;
    for (int kt = 0; kt < nk; kt++) {
        *(uint4*)&As[row][kq]     = make_uint4(f2tf(pa0.x), f2tf(pa0.y), f2tf(pa0.z), f2tf(pa0.w));
        *(uint4*)&As[row][kq + 4] = make_uint4(f2tf(pa1.x), f2tf(pa1.y), f2tf(pa1.z), f2tf(pa1.w));
        *(uint4*)&Bs[row][kq]     = make_uint4(f2tf(pb0.x), f2tf(pb0.y), f2tf(pb0.z), f2tf(pb0.w));
        *(uint4*)&Bs[row][kq + 4] = make_uint4(f2tf(pb1.x), f2tf(pb1.y), f2tf(pb1.z), f2tf(pb1.w));
        __syncthreads();
        if (kt + 1 < nk) {
            const float* Ap2 = Ap + (size_t)(kt + 1) * 16;
            const float* Wp2 = Wp + (size_t)(kt + 1) * 16;
            pa0 = *(const float4*)Ap2; pa1 = *(const float4*)(Ap2 + 4);
            pb0 = *(const float4*)Wp2; pb1 = *(const float4*)(Wp2 + 4);
        }
#pragma unroll
        for (int kh = 0; kh < 16; kh += 8) {
            unsigned af[4][4], bf[4][2];
#pragma unroll
            for (int mt = 0; mt < 4; mt++) {
                int r0 = wm + mt*16 + grp;
                af[mt][0] = As[r0][kh + qd];
                af[mt][1] = As[r0 + 8][kh + qd];
                af[mt][2] = As[r0][kh + qd + 4];
                af[mt][3] = As[r0 + 8][kh + qd + 4];
            }
#pragma unroll
            for (int nt = 0; nt < 4; nt++) {
                int n0 = wn + nt*8 + grp;
                bf[nt][0] = Bs[n0][kh + qd];
                bf[nt][1] = Bs[n0][kh + qd + 4];
            }
#pragma unroll
            for (int mt = 0; mt < 4; mt++)
#pragma unroll
                for (int nt = 0; nt < 4; nt++)
                    mma_tf32(c[mt][nt][0], c[mt][nt][1], c[mt][nt][2], c[mt][nt][3],
                             af[mt][0], af[mt][1], af[mt][2], af[mt][3],
                             bf[nt][0], bf[nt][1]);
        }
        __syncthreads();
    }

#pragma unroll
    for (int mt = 0; mt < 4; mt++) {
        int r0 = bm + wm + mt*16 + grp;
#pragma unroll
        for (int nt = 0; nt < 4; nt++) {
            int cb = bn + wn + nt*8 + 2*qd;
            float bi0 = bias[cb], bi1 = bias[cb + 1];
            float v0 = c[mt][nt][0] + bi0;
            float v1 = c[mt][nt][1] + bi1;
            float v2 = c[mt][nt][2] + bi0;
            float v3 = c[mt][nt][3] + bi1;
            if (relu) {
                v0 = fmaxf(v0, 0.f); v1 = fmaxf(v1, 0.f);
                v2 = fmaxf(v2, 0.f); v3 = fmaxf(v3, 0.f);
            }
            *(float2*)(C + (size_t)r0*N + cb)       = make_float2(v0, v1);
            *(float2*)(C + (size_t)(r0 + 8)*N + cb) = make_float2(v2, v3);
        }
    }
}

// --------- FP16 flash attention: one block per (b,h), 2 blocks/SM ---------
// Ks [440][40]h, VT [32][456]h, P per-warp [16][104]h
#define KST 40
#define VST 456
#define PST 104
#define ATTN_SMEM ((440*KST + 32*VST + 8*16*PST)*2)
__global__ __launch_bounds__(256, 2) void k_attn(const float* __restrict__ abias)
{
    extern __shared__ __half hsm[];
    __half* Ks = hsm;                    // [440][KST]
    __half* VT = hsm + 440*KST;          // [32][VST]
    __half* Ps = VT + 32*VST;            // 8 x [16][PST]
    int b = blockIdx.x >> 3, hh = blockIdx.x & 7;
    int tid = threadIdx.x, lane = tid & 31, warp = tid >> 5;
    int grp = lane >> 2, qd = lane & 3;
    const float* qkvb = g_qkv + (size_t)b * SSEQ * 768;

    for (int idx = tid; idx < SSEQ*32; idx += 256) {
        int s = idx >> 5, d = idx & 31;
        Ks[s*KST + d]  = __float2half_rn(qkvb[(size_t)s*768 + 256 + hh*32 + d]);
        VT[d*VST + s]  = __float2half_rn(qkvb[(size_t)s*768 + 512 + hh*32 + d]);
    }
    __syncthreads();

    __half* Pw = Ps + warp * 16 * PST;
    const float scale = 0.17677669529663687f;

    for (int mt = warp; mt < 28; mt += 8) {
        int q0 = mt * 16;
        int qr0 = q0 + grp;      if (qr0 > 439) qr0 = 439;
        int qr1 = q0 + grp + 8;  if (qr1 > 439) qr1 = 439;
        const float* Qp0 = qkvb + (size_t)qr0*768 + hh*32;
        const float* Qp1 = qkvb + (size_t)qr1*768 + hh*32;
        unsigned aq[2][4];
#pragma unroll
        for (int ks = 0; ks < 2; ks++) {
            aq[ks][0] = packh2(Qp0[ks*16 + 2*qd],     Qp0[ks*16 + 2*qd + 1]);
            aq[ks][1] = packh2(Qp1[ks*16 + 2*qd],     Qp1[ks*16 + 2*qd + 1]);
            aq[ks][2] = packh2(Qp0[ks*16 + 2*qd + 8], Qp0[ks*16 + 2*qd + 9]);
            aq[ks][3] = packh2(Qp1[ks*16 + 2*qd + 8], Qp1[ks*16 + 2*qd + 9]);
        }
        const float* bp0 = abias + (size_t)qr0 * SSEQ;
        const float* bp1 = abias + (size_t)qr1 * SSEQ;

        float o[4][4];
#pragma unroll
        for (int dc = 0; dc < 4; dc++)
#pragma unroll
            for (int r = 0; r < 4; r++) o[dc][r] = 0.f;
        float m0 = -1e30f, m1 = -1e30f, l0 = 0.f, l1 = 0.f;

        for (int ch = 0; ch < 5; ch++) {
            int kbase = ch * 88;
            float cs[11][4];
#pragma unroll
            for (int nc = 0; nc < 11; nc++) {
                int n0 = kbase + nc*8;
                float c0 = 0.f, c1 = 0.f, c2 = 0.f, c3 = 0.f;
                const __half* kr = Ks + (n0 + grp)*KST;
#pragma unroll
                for (int ks = 0; ks < 2; ks++) {
                    unsigned b0 = *(const unsigned*)(kr + ks*16 + 2*qd);
                    unsigned b1 = *(const unsigned*)(kr + ks*16 + 2*qd + 8);
                    mma_f16_k16(c0, c1, c2, c3,
                                aq[ks][0], aq[ks][1], aq[ks][2], aq[ks][3], b0, b1);
                }
                float2 bb0 = *(const float2*)(bp0 + n0 + 2*qd);
                float2 bb1 = *(const float2*)(bp1 + n0 + 2*qd);
                cs[nc][0] = fmaf(c0, scale, bb0.x);
                cs[nc][1] = fmaf(c1, scale, bb0.y);
                cs[nc][2] = fmaf(c2, scale, bb1.x);
                cs[nc][3] = fmaf(c3, scale, bb1.y);
            }
            float cm0 = -1e30f, cm1 = -1e30f;
#pragma unroll
            for (int nc = 0; nc < 11; nc++) {
                cm0 = fmaxf(cm0, fmaxf(cs[nc][0], cs[nc][1]));
                cm1 = fmaxf(cm1, fmaxf(cs[nc][2], cs[nc][3]));
            }
            cm0 = fmaxf(cm0, __shfl_xor_sync(~0u, cm0, 1));
            cm0 = fmaxf(cm0, __shfl_xor_sync(~0u, cm0, 2));
            cm1 = fmaxf(cm1, __shfl_xor_sync(~0u, cm1, 1));
            cm1 = fmaxf(cm1, __shfl_xor_sync(~0u, cm1, 2));
            float nm0 = fmaxf(m0, cm0), nm1 = fmaxf(m1, cm1);
            float f0 = __expf(m0 - nm0), f1 = __expf(m1 - nm1);
            m0 = nm0; m1 = nm1;
            l0 *= f0; l1 *= f1;
#pragma unroll
            for (int dc = 0; dc < 4; dc++) {
                o[dc][0] *= f0; o[dc][1] *= f0;
                o[dc][2] *= f1; o[dc][3] *= f1;
            }
            float ps0 = 0.f, ps1 = 0.f;
#pragma unroll
            for (int nc = 0; nc < 11; nc++) {
                float e0 = __expf(cs[nc][0] - m0);
                float e1 = __expf(cs[nc][1] - m0);
                float e2 = __expf(cs[nc][2] - m1);
                float e3 = __expf(cs[nc][3] - m1);
                ps0 += e0 + e1; ps1 += e2 + e3;
                *(unsigned*)(Pw + grp*PST + nc*8 + 2*qd)       = packh2(e0, e1);
                *(unsigned*)(Pw + (grp + 8)*PST + nc*8 + 2*qd) = packh2(e2, e3);
            }
            ps0 += __shfl_xor_sync(~0u, ps0, 1);
            ps0 += __shfl_xor_sync(~0u, ps0, 2);
            ps1 += __shfl_xor_sync(~0u, ps1, 1);
            ps1 += __shfl_xor_sync(~0u, ps1, 2);
            l0 += ps0; l1 += ps1;
            __syncwarp();
            // P @ V: 5 x k16 + 1 x k8 tail (88 keys)
#pragma unroll
            for (int ks = 0; ks < 5; ks++) {
                unsigned ap0 = *(const unsigned*)(Pw + grp*PST + ks*16 + 2*qd);
                unsigned ap1 = *(const unsigned*)(Pw + (grp + 8)*PST + ks*16 + 2*qd);
                unsigned ap2 = *(const unsigned*)(Pw + grp*PST + ks*16 + 2*qd + 8);
                unsigned ap3 = *(const unsigned*)(Pw + (grp + 8)*PST + ks*16 + 2*qd + 8);
#pragma unroll
                for (int dc = 0; dc < 4; dc++) {
                    const __half* vr = VT + (dc*8 + grp)*VST + kbase + ks*16;
                    unsigned b0 = *(const unsigned*)(vr + 2*qd);
                    unsigned b1 = *(const unsigned*)(vr + 2*qd + 8);
                    mma_f16_k16(o[dc][0], o[dc][1], o[dc][2], o[dc][3],
                                ap0, ap1, ap2, ap3, b0, b1);
                }
            }
            {
                unsigned ap0 = *(const unsigned*)(Pw + grp*PST + 80 + 2*qd);
                unsigned ap1 = *(const unsigned*)(Pw + (grp + 8)*PST + 80 + 2*qd);
#pragma unroll
                for (int dc = 0; dc < 4; dc++) {
                    const __half* vr = VT + (dc*8 + grp)*VST + kbase + 80;
                    unsigned b0 = *(const unsigned*)(vr + 2*qd);
                    mma_f16_k8(o[dc][0], o[dc][1], o[dc][2], o[dc][3], ap0, ap1, b0);
                }
            }
            __syncwarp();
        }
        float inv0 = 1.f / l0, inv1 = 1.f / l1;
        int qa = q0 + grp, qb = q0 + grp + 8;
#pragma unroll
        for (int dc = 0; dc < 4; dc++) {
            int dcol = hh*32 + dc*8 + 2*qd;
            if (qa < SSEQ)
                *(float2*)(g_t1 + ((size_t)b*SSEQ + qa)*DDIM + dcol) =
                    make_float2(o[dc][0]*inv0, o[dc][1]*inv0);
            if (qb < SSEQ)
                *(float2*)(g_t1 + ((size_t)b*SSEQ + qb)*DDIM + dcol) =
                    make_float2(o[dc][2]*inv1, o[dc][3]*inv1);
        }
    }
}

// ------------- fused residual + layernorm (in place on g_h) -------------
__global__ __launch_bounds__(256) void k_ln(const float* __restrict__ add,
                                            const float* __restrict__ gam,
                                            const float* __restrict__ bet)
{
    int r = blockIdx.x, d = threadIdx.x;
    size_t i = (size_t)r*DDIM + d;
    float v = g_h[i] + add[i];
    float s1 = v, s2 = v*v;
#pragma unroll
    for (int o = 16; o > 0; o >>= 1) {
        s1 += __shfl_xor_sync(~0u, s1, o);
        s2 += __shfl_xor_sync(~0u, s2, o);
    }
    __shared__ float a1s[8], a2s[8];
    if ((d & 31) == 0) { a1s[d>>5] = s1; a2s[d>>5] = s2; }
    __syncthreads();
    float t1 = 0.f, t2 = 0.f;
#pragma unroll
    for (int j = 0; j < 8; j++) { t1 += a1s[j]; t2 += a2s[j]; }
    float m = t1 * (1.f/256.f);
    float var = t2 * (1.f/256.f) - m*m;
    g_h[i] = (v - m) * rsqrtf(var + 1e-5f) * gam[d] + bet[d];
}

// --------- TF32 mma conv: canvas implicit GEMM, one block per (b, group) ---------
#define CVST 808
#define WST  36
#define CONV_SMEM ((32*CVST + 9*32*WST)*4)
__global__ __launch_bounds__(256, 1) void k_conv(
    const float* __restrict__ cw1, const float* __restrict__ cb1,
    const float* __restrict__ cw2, const float* __restrict__ cb2,
    const float* __restrict__ cw3, const float* __restrict__ cb3,
    float* __restrict__ out)
{
    extern __shared__ unsigned usm[];
    unsigned* cx  = usm;                 // [32][CVST]
    unsigned* swt = usm + 32*CVST;       // [9][32][WST]
    int b = blockIdx.x >> 3, gch = blockIdx.x & 7;
    int tid = threadIdx.x, lane = tid & 31, warp = tid >> 5;
    int grp = lane >> 2, qd = lane & 3;
    const float* hb = g_h + (size_t)b * SSEQ * DDIM;

    for (int i = tid; i < 32*CVST; i += 256) cx[i] = 0u;
    __syncthreads();
    for (int idx = tid; idx < SSEQ*32; idx += 256) {
        int p = idx >> 5, c = idx & 31;
        int cidx = p + 6*(p/22) + 87;
        cx[c*CVST + cidx] = f2tf(hb[(size_t)p*DDIM + gch*32 + c]);
    }

    const float* cws[3] = {cw1, cw2, cw3};
    const float* cbs[3] = {cb1, cb2, cb3};

    int mt0 = warp;
#pragma unroll
    for (int half = 0; half < 2; half++) {
        int tA = mt0 + 16*half;
        int pxA0 = tA*16 + grp;
        int pxA1 = pxA0 + 8;
        int pxB0 = (tA + 8)*16 + grp;
        int pxB1 = pxB0 + 8;
        int ciA0 = pxA0 + 6*(pxA0/22) + 87;
        int ciA1 = pxA1 + 6*(pxA1/22) + 87;
        int ciB0 = pxB0 + 6*(pxB0/22) + 87;
        int ciB1 = pxB1 + 6*(pxB1/22) + 87;

        float tot[2][4][4];
#pragma unroll
        for (int p = 0; p < 2; p++)
#pragma unroll
            for (int nt = 0; nt < 4; nt++)
#pragma unroll
                for (int r = 0; r < 4; r++) tot[p][nt][r] = 0.f;

        for (int cv = 0; cv < 3; cv++) {
            int dil = cv + 1;
            __syncthreads();
            const float* src = cws[cv] + (size_t)gch * 32 * 288;
            for (int i = tid; i < 32*288; i += 256) {
                int oc = i / 288, rem = i - oc*288;
                int ic = rem / 9, t = rem - ic*9;
                swt[t*32*WST + oc*WST + ic] = f2tf(src[i]);
            }
            __syncthreads();

            float acc[2][4][4];
#pragma unroll
            for (int p = 0; p < 2; p++)
#pragma unroll
                for (int nt = 0; nt < 4; nt++)
#pragma unroll
                    for (int r = 0; r < 4; r++) acc[p][nt][r] = 0.f;

            for (int t = 0; t < 9; t++) {
                int sh = (t/3 - 1)*dil*28 + (t%3 - 1)*dil;
                const unsigned* wt = swt + t*32*WST;
#pragma unroll
                for (int ks = 0; ks < 4; ks++) {
                    int ic0 = ks*8 + qd;
                    const unsigned* r0 = cx + ic0*CVST + sh;
                    const unsigned* r1 = cx + (ic0 + 4)*CVST + sh;
                    unsigned aA0 = r0[ciA0], aA1 = r0[ciA1];
                    unsigned aA2 = r1[ciA0], aA3 = r1[ciA1];
                    unsigned aB0 = r0[ciB0], aB1 = r0[ciB1];
                    unsigned aB2 = r1[ciB0], aB3 = r1[ciB1];
#pragma unroll
                    for (int nt = 0; nt < 4; nt++) {
                        unsigned b0 = wt[(nt*8 + grp)*WST + ic0];
                        unsigned b1 = wt[(nt*8 + grp)*WST + ic0 + 4];
                        mma_tf32(acc[0][nt][0], acc[0][nt][1], acc[0][nt][2], acc[0][nt][3],
                                 aA0, aA1, aA2, aA3, b0, b1);
                        mma_tf32(acc[1][nt][0], acc[1][nt][1], acc[1][nt][2], acc[1][nt][3],
                                 aB0, aB1, aB2, aB3, b0, b1);
                    }
                }
            }
#pragma unroll
            for (int nt = 0; nt < 4; nt++) {
                float bi0 = cbs[cv][gch*32 + nt*8 + 2*qd];
                float bi1 = cbs[cv][gch*32 + nt*8 + 2*qd + 1];
#pragma unroll
                for (int p = 0; p < 2; p++) {
                    tot[p][nt][0] += fmaxf(acc[p][nt][0] + bi0, 0.f);
                    tot[p][nt][1] += fmaxf(acc[p][nt][1] + bi1, 0.f);
                    tot[p][nt][2] += fmaxf(acc[p][nt][2] + bi0, 0.f);
                    tot[p][nt][3] += fmaxf(acc[p][nt][3] + bi1, 0.f);
                }
            }
        }

        float* ob = out + (size_t)b * SSEQ * DDIM;
#pragma unroll
        for (int p = 0; p < 2; p++) {
            int px0 = (tA + 8*p)*16 + grp;
            int px1 = px0 + 8;
#pragma unroll
            for (int nt = 0; nt < 4; nt++) {
                int ch = gch*32 + nt*8 + 2*qd;
                if (px0 < SSEQ) {
                    float r0 = hb[(size_t)px0*DDIM + ch];
                    float r1 = hb[(size_t)px0*DDIM + ch + 1];
                    *(float2*)(ob + (size_t)px0*DDIM + ch) =
                        make_float2(0.5f*(r0 + tot[p][nt][0]), 0.5f*(r1 + tot[p][nt][1]));
                }
                if (px1 < SSEQ) {
                    float r2 = hb[(size_t)px1*DDIM + ch];
                    float r3 = hb[(size_t)px1*DDIM + ch + 1];
                    *(float2*)(ob + (size_t)px1*DDIM + ch) =
                        make_float2(0.5f*(r2 + tot[p][nt][2]), 0.5f*(r3 + tot[p][nt][3]));
                }
            }
        }
        __syncthreads();
    }
}

// ------------------------------ launcher ------------------------------
extern "C" void kernel_launch(void* const* d_in, const int* in_sizes, int n_in,
                              void* d_out, int out_size)
{
    const int* x    = (const int*)d_in[0];
    const float* ev   = (const float*)d_in[2];
    const float* px   = (const float*)d_in[3];
    const float* py   = (const float*)d_in[4];
    const float* st   = (const float*)d_in[5];
    const int* tkx = (const int*)d_in[6];
    const int* tky = (const int*)d_in[7];
    const int* tks = (const int*)d_in[8];
    const float* abias = (const float*)d_in[9];
    const float* Wqkv = (const float*)d_in[10];
    const float* bqkv = (const float*)d_in[11];
    const float* Wo   = (const float*)d_in[12];
    const float* bo   = (const float*)d_in[13];
    const float* W1   = (const float*)d_in[14];
    const float* b1   = (const float*)d_in[15];
    const float* W2   = (const float*)d_in[16];
    const float* b2   = (const float*)d_in[17];
    const float* ln1s = (const float*)d_in[18];
    const float* ln1b = (const float*)d_in[19];
    const float* ln2s = (const float*)d_in[20];
    const float* ln2b = (const float*)d_in[21];
    const float* cw1  = (const float*)d_in[22];
    const float* cb1  = (const float*)d_in[23];
    const float* cw2  = (const float*)d_in[24];
    const float* cb2  = (const float*)d_in[25];
    const float* cw3  = (const float*)d_in[26];
    const float* cb3  = (const float*)d_in[27];
    float* out = (float*)d_out;

    float *hP, *qkvP, *t1P, *t2P;
    cudaGetSymbolAddress((void**)&hP,   g_h);
    cudaGetSymbolAddress((void**)&qkvP, g_qkv);
    cudaGetSymbolAddress((void**)&t1P,  g_t1);
    cudaGetSymbolAddress((void**)&t2P,  g_t2);

    cudaFuncSetAttribute(k_attn, cudaFuncAttributeMaxDynamicSharedMemorySize, ATTN_SMEM);
    cudaFuncSetAttribute(k_conv, cudaFuncAttributeMaxDynamicSharedMemorySize, CONV_SMEM);

    k_embed<<<BS_, 256>>>(x, ev, px, py, st, tkx, tky, tks);

    for (int l = 0; l < LNUM; l++) {
        k_gemm<<<dim3(6, 220), 256>>>(hP, Wqkv + (size_t)l*768*256, bqkv + l*768,
                                      qkvP, BS_, 768, 256, 0);
        k_attn<<<BB*HN, 256, ATTN_SMEM>>>(abias);
        k_gemm<<<dim3(2, 220), 256>>>(t1P, Wo + (size_t)l*256*256, bo + l*256,
                                      t2P, BS_, 256, 256, 0);
        k_ln<<<BS_, 256>>>(t2P, ln1s + l*256, ln1b + l*256);
        k_gemm<<<dim3(4, 220), 256>>>(hP, W1 + (size_t)l*512*256, b1 + l*512,
                                      t1P, BS_, 512, 256, 1);
        k_gemm<<<dim3(2, 220), 256>>>(t1P, W2 + (size_t)l*256*512, b2 + l*256,
                                      t2P, BS_, 256, 512, 0);
        k_ln<<<BS_, 256>>>(t2P, ln2s + l*256, ln2b + l*256);
        float* cout = (l == LNUM-1) ? out : hP;
        k_conv<<<BB*HN, 256, CONV_SMEM>>>(cw1 + (size_t)l*256*288, cb1 + l*256,
                                          cw2 + (size_t)l*256*288, cb2 + l*256,
                                          cw3 + (size_t)l*256*288, cb3 + l*256,
                                          cout);
    }
}

// round 10
// speedup vs baseline: 4.6922x; 1.3466x over previous
#include <cuda_runtime.h>
#include <cuda_bf16.h>
#include <cuda_fp16.h>

#define BB 64
#define SSEQ 440
#define DDIM 256
#define HN 8
#define FFD 512
#define LNUM 6
#define BS_ (BB*SSEQ)   // 28160

// ------------ static device scratch (no allocation) ------------
__device__ float g_h[(size_t)BS_*DDIM];
__device__ float g_qkv[(size_t)BS_*3*DDIM];
__device__ float g_t1[(size_t)BS_*FFD];
__device__ float g_t2[(size_t)BS_*DDIM];

__device__ __forceinline__ void mma_f16_k16(float& c0, float& c1, float& c2, float& c3,
                                            unsigned a0, unsigned a1, unsigned a2, unsigned a3,
                                            unsigned b0, unsigned b1)
{
    asm volatile(
        "mma.sync.aligned.m16n8k16.row.col.f32.f16.f16.f32 "
        "{%0,%1,%2,%3}, {%4,%5,%6,%7}, {%8,%9}, {%0,%1,%2,%3};"
        : "+f"(c0), "+f"(c1), "+f"(c2), "+f"(c3)
        : "r"(a0), "r"(a1), "r"(a2), "r"(a3), "r"(b0), "r"(b1));
}

__device__ __forceinline__ void mma_f16_k8(float& c0, float& c1, float& c2, float& c3,
                                           unsigned a0, unsigned a1, unsigned b0)
{
    asm volatile(
        "mma.sync.aligned.m16n8k8.row.col.f32.f16.f16.f32 "
        "{%0,%1,%2,%3}, {%4,%5}, {%6}, {%0,%1,%2,%3};"
        : "+f"(c0), "+f"(c1), "+f"(c2), "+f"(c3)
        : "r"(a0), "r"(a1), "r"(b0));
}

__device__ __forceinline__ unsigned packh2(float a, float b) {
    __half2 h = __floats2half2_rn(a, b);
    return *(unsigned*)&h;
}

// ------------------------ embedding ------------------------
__global__ void k_embed(const int* __restrict__ x,
                        const float* __restrict__ ev, const float* __restrict__ px,
                        const float* __restrict__ py, const float* __restrict__ st,
                        const int* __restrict__ tkx, const int* __restrict__ tky,
                        const int* __restrict__ tks)
{
    int bs = blockIdx.x;
    int s = bs % SSEQ;
    int d = threadIdx.x;
    int xi = x[bs];
    g_h[(size_t)bs*DDIM + d] =
        ev[xi*DDIM + d] + px[tkx[s]*DDIM + d] + py[tky[s]*DDIM + d] + st[tks[s]*DDIM + d];
}

// ---- FP16 tensor-core GEMM: C[M,N] = A[M,K] @ W[N,K]^T + bias (opt relu) ----
// 128x128 tile, k-step 16 (one m16n8k16 mma per warp-tile per stage)
__global__ __launch_bounds__(256, 2) void k_gemm(
    const float* __restrict__ A, const float* __restrict__ W,
    const float* __restrict__ bias, float* __restrict__ C,
    int M, int N, int K, int relu)
{
    __shared__ unsigned As[128][12];   // half2 words, stride 12 (conflict-free frags)
    __shared__ unsigned Bs[128][12];
    int tid = threadIdx.x;
    int bm = blockIdx.y * 128, bn = blockIdx.x * 128;
    int row = tid >> 1, wq = (tid & 1) * 4;   // word base in row
    const float* Ap = A + (size_t)(bm + row) * K + (tid & 1) * 8;
    const float* Wp = W + (size_t)(bn + row) * K + (tid & 1) * 8;
    float4 pa0 = *(const float4*)Ap;
    float4 pa1 = *(const float4*)(Ap + 4);
    float4 pb0 = *(const float4*)Wp;
    float4 pb1 = *(const float4*)(Wp + 4);

    int lane = tid & 31, warp = tid >> 5;
    int wm = (warp & 1) * 64, wn = (warp >> 1) * 32;
    int grp = lane >> 2, qd = lane & 3;

    float c[4][4][4];
#pragma unroll
    for (int mt = 0; mt < 4; mt++)
#pragma unroll
        for (int nt = 0; nt < 4; nt++)
#pragma unroll
            for (int r = 0; r < 4; r++) c[mt][nt][r] = 0.f;

    int nk = K >> 4;
    for (int kt = 0; kt < nk; kt++) {
        *(uint4*)&As[row][wq] = make_uint4(packh2(pa0.x, pa0.y), packh2(pa0.z, pa0.w),
                                           packh2(pa1.x, pa1.y), packh2(pa1.z, pa1.w));
        *(uint4*)&Bs[row][wq] = make_uint4(packh2(pb0.x, pb0.y), packh2(pb0.z, pb0.w),
                                           packh2(pb1.x, pb1.y), packh2(pb1.z, pb1.w));
        __syncthreads();
        if (kt + 1 < nk) {
            const float* Ap2 = Ap + (size_t)(kt + 1) * 16;
            const float* Wp2 = Wp + (size_t)(kt + 1) * 16;
            pa0 = *(const float4*)Ap2; pa1 = *(const float4*)(Ap2 + 4);
            pb0 = *(const float4*)Wp2; pb1 = *(const float4*)(Wp2 + 4);
        }
        unsigned af[4][4], bf[4][2];
#pragma unroll
        for (int mt = 0; mt < 4; mt++) {
            int r0 = wm + mt*16 + grp;
            af[mt][0] = As[r0][qd];
            af[mt][1] = As[r0 + 8][qd];
            af[mt][2] = As[r0][qd + 4];
            af[mt][3] = As[r0 + 8][qd + 4];
        }
#pragma unroll
        for (int nt = 0; nt < 4; nt++) {
            int n0 = wn + nt*8 + grp;
            bf[nt][0] = Bs[n0][qd];
            bf[nt][1] = Bs[n0][qd + 4];
        }
#pragma unroll
        for (int mt = 0; mt < 4; mt++)
#pragma unroll
            for (int nt = 0; nt < 4; nt++)
                mma_f16_k16(c[mt][nt][0], c[mt][nt][1], c[mt][nt][2], c[mt][nt][3],
                            af[mt][0], af[mt][1], af[mt][2], af[mt][3],
                            bf[nt][0], bf[nt][1]);
        __syncthreads();
    }

#pragma unroll
    for (int mt = 0; mt < 4; mt++) {
        int r0 = bm + wm + mt*16 + grp;
#pragma unroll
        for (int nt = 0; nt < 4; nt++) {
            int cb = bn + wn + nt*8 + 2*qd;
            float bi0 = bias[cb], bi1 = bias[cb + 1];
            float v0 = c[mt][nt][0] + bi0;
            float v1 = c[mt][nt][1] + bi1;
            float v2 = c[mt][nt][2] + bi0;
            float v3 = c[mt][nt][3] + bi1;
            if (relu) {
                v0 = fmaxf(v0, 0.f); v1 = fmaxf(v1, 0.f);
                v2 = fmaxf(v2, 0.f); v3 = fmaxf(v3, 0.f);
            }
            *(float2*)(C + (size_t)r0*N + cb)       = make_float2(v0, v1);
            *(float2*)(C + (size_t)(r0 + 8)*N + cb) = make_float2(v2, v3);
        }
    }
}

// --------- FP16 flash attention: one block per (b,h), 224 threads, 2 blocks/SM ---------
#define KST 40
#define VST 456
#define PST 104
#define ATTN_SMEM ((440*KST + 32*VST + 7*16*PST)*2)
__global__ __launch_bounds__(224, 2) void k_attn(const float* __restrict__ abias)
{
    extern __shared__ __half hsm[];
    __half* Ks = hsm;                    // [440][KST]
    __half* VT = hsm + 440*KST;          // [32][VST]
    __half* Ps = VT + 32*VST;            // 7 x [16][PST]
    int b = blockIdx.x >> 3, hh = blockIdx.x & 7;
    int tid = threadIdx.x, lane = tid & 31, warp = tid >> 5;
    int grp = lane >> 2, qd = lane & 3;
    const float* qkvb = g_qkv + (size_t)b * SSEQ * 768;

    for (int idx = tid; idx < SSEQ*32; idx += 224) {
        int s = idx >> 5, d = idx & 31;
        Ks[s*KST + d]  = __float2half_rn(qkvb[(size_t)s*768 + 256 + hh*32 + d]);
        VT[d*VST + s]  = __float2half_rn(qkvb[(size_t)s*768 + 512 + hh*32 + d]);
    }
    __syncthreads();

    __half* Pw = Ps + warp * 16 * PST;
    const float scale = 0.17677669529663687f;

    for (int mt = warp; mt < 28; mt += 7) {
        int q0 = mt * 16;
        int qr0 = q0 + grp;      if (qr0 > 439) qr0 = 439;
        int qr1 = q0 + grp + 8;  if (qr1 > 439) qr1 = 439;
        const float* Qp0 = qkvb + (size_t)qr0*768 + hh*32;
        const float* Qp1 = qkvb + (size_t)qr1*768 + hh*32;
        unsigned aq[2][4];
#pragma unroll
        for (int ks = 0; ks < 2; ks++) {
            aq[ks][0] = packh2(Qp0[ks*16 + 2*qd],     Qp0[ks*16 + 2*qd + 1]);
            aq[ks][1] = packh2(Qp1[ks*16 + 2*qd],     Qp1[ks*16 + 2*qd + 1]);
            aq[ks][2] = packh2(Qp0[ks*16 + 2*qd + 8], Qp0[ks*16 + 2*qd + 9]);
            aq[ks][3] = packh2(Qp1[ks*16 + 2*qd + 8], Qp1[ks*16 + 2*qd + 9]);
        }
        const float* bp0 = abias + (size_t)qr0 * SSEQ;
        const float* bp1 = abias + (size_t)qr1 * SSEQ;

        float o[4][4];
#pragma unroll
        for (int dc = 0; dc < 4; dc++)
#pragma unroll
            for (int r = 0; r < 4; r++) o[dc][r] = 0.f;
        float m0 = -1e30f, m1 = -1e30f, l0 = 0.f, l1 = 0.f;

        for (int ch = 0; ch < 5; ch++) {
            int kbase = ch * 88;
            float cs[11][4];
#pragma unroll
            for (int nc = 0; nc < 11; nc++) {
                int n0 = kbase + nc*8;
                float c0 = 0.f, c1 = 0.f, c2 = 0.f, c3 = 0.f;
                const __half* kr = Ks + (n0 + grp)*KST;
#pragma unroll
                for (int ks = 0; ks < 2; ks++) {
                    unsigned b0 = *(const unsigned*)(kr + ks*16 + 2*qd);
                    unsigned b1 = *(const unsigned*)(kr + ks*16 + 2*qd + 8);
                    mma_f16_k16(c0, c1, c2, c3,
                                aq[ks][0], aq[ks][1], aq[ks][2], aq[ks][3], b0, b1);
                }
                float2 bb0 = *(const float2*)(bp0 + n0 + 2*qd);
                float2 bb1 = *(const float2*)(bp1 + n0 + 2*qd);
                cs[nc][0] = fmaf(c0, scale, bb0.x);
                cs[nc][1] = fmaf(c1, scale, bb0.y);
                cs[nc][2] = fmaf(c2, scale, bb1.x);
                cs[nc][3] = fmaf(c3, scale, bb1.y);
            }
            float cm0 = -1e30f, cm1 = -1e30f;
#pragma unroll
            for (int nc = 0; nc < 11; nc++) {
                cm0 = fmaxf(cm0, fmaxf(cs[nc][0], cs[nc][1]));
                cm1 = fmaxf(cm1, fmaxf(cs[nc][2], cs[nc][3]));
            }
            cm0 = fmaxf(cm0, __shfl_xor_sync(~0u, cm0, 1));
            cm0 = fmaxf(cm0, __shfl_xor_sync(~0u, cm0, 2));
            cm1 = fmaxf(cm1, __shfl_xor_sync(~0u, cm1, 1));
            cm1 = fmaxf(cm1, __shfl_xor_sync(~0u, cm1, 2));
            float nm0 = fmaxf(m0, cm0), nm1 = fmaxf(m1, cm1);
            float f0 = __expf(m0 - nm0), f1 = __expf(m1 - nm1);
            m0 = nm0; m1 = nm1;
            l0 *= f0; l1 *= f1;
#pragma unroll
            for (int dc = 0; dc < 4; dc++) {
                o[dc][0] *= f0; o[dc][1] *= f0;
                o[dc][2] *= f1; o[dc][3] *= f1;
            }
            float ps0 = 0.f, ps1 = 0.f;
#pragma unroll
            for (int nc = 0; nc < 11; nc++) {
                float e0 = __expf(cs[nc][0] - m0);
                float e1 = __expf(cs[nc][1] - m0);
                float e2 = __expf(cs[nc][2] - m1);
                float e3 = __expf(cs[nc][3] - m1);
                ps0 += e0 + e1; ps1 += e2 + e3;
                *(unsigned*)(Pw + grp*PST + nc*8 + 2*qd)       = packh2(e0, e1);
                *(unsigned*)(Pw + (grp + 8)*PST + nc*8 + 2*qd) = packh2(e2, e3);
            }
            ps0 += __shfl_xor_sync(~0u, ps0, 1);
            ps0 += __shfl_xor_sync(~0u, ps0, 2);
            ps1 += __shfl_xor_sync(~0u, ps1, 1);
            ps1 += __shfl_xor_sync(~0u, ps1, 2);
            l0 += ps0; l1 += ps1;
            __syncwarp();
#pragma unroll
            for (int ks = 0; ks < 5; ks++) {
                unsigned ap0 = *(const unsigned*)(Pw + grp*PST + ks*16 + 2*qd);
                unsigned ap1 = *(const unsigned*)(Pw + (grp + 8)*PST + ks*16 + 2*qd);
                unsigned ap2 = *(const unsigned*)(Pw + grp*PST + ks*16 + 2*qd + 8);
                unsigned ap3 = *(const unsigned*)(Pw + (grp + 8)*PST + ks*16 + 2*qd + 8);
#pragma unroll
                for (int dc = 0; dc < 4; dc++) {
                    const __half* vr = VT + (dc*8 + grp)*VST + kbase + ks*16;
                    unsigned b0 = *(const unsigned*)(vr + 2*qd);
                    unsigned b1 = *(const unsigned*)(vr + 2*qd + 8);
                    mma_f16_k16(o[dc][0], o[dc][1], o[dc][2], o[dc][3],
                                ap0, ap1, ap2, ap3, b0, b1);
                }
            }
            {
                unsigned ap0 = *(const unsigned*)(Pw + grp*PST + 80 + 2*qd);
                unsigned ap1 = *(const unsigned*)(Pw + (grp + 8)*PST + 80 + 2*qd);
#pragma unroll
                for (int dc = 0; dc < 4; dc++) {
                    const __half* vr = VT + (dc*8 + grp)*VST + kbase + 80;
                    unsigned b0 = *(const unsigned*)(vr + 2*qd);
                    mma_f16_k8(o[dc][0], o[dc][1], o[dc][2], o[dc][3], ap0, ap1, b0);
                }
            }
            __syncwarp();
        }
        float inv0 = 1.f / l0, inv1 = 1.f / l1;
        int qa = q0 + grp, qb = q0 + grp + 8;
#pragma unroll
        for (int dc = 0; dc < 4; dc++) {
            int dcol = hh*32 + dc*8 + 2*qd;
            if (qa < SSEQ)
                *(float2*)(g_t1 + ((size_t)b*SSEQ + qa)*DDIM + dcol) =
                    make_float2(o[dc][0]*inv0, o[dc][1]*inv0);
            if (qb < SSEQ)
                *(float2*)(g_t1 + ((size_t)b*SSEQ + qb)*DDIM + dcol) =
                    make_float2(o[dc][2]*inv1, o[dc][3]*inv1);
        }
    }
}

// ------------- fused residual + layernorm (in place on g_h) -------------
__global__ __launch_bounds__(256) void k_ln(const float* __restrict__ add,
                                            const float* __restrict__ gam,
                                            const float* __restrict__ bet)
{
    int r = blockIdx.x, d = threadIdx.x;
    size_t i = (size_t)r*DDIM + d;
    float v = g_h[i] + add[i];
    float s1 = v, s2 = v*v;
#pragma unroll
    for (int o = 16; o > 0; o >>= 1) {
        s1 += __shfl_xor_sync(~0u, s1, o);
        s2 += __shfl_xor_sync(~0u, s2, o);
    }
    __shared__ float a1s[8], a2s[8];
    if ((d & 31) == 0) { a1s[d>>5] = s1; a2s[d>>5] = s2; }
    __syncthreads();
    float t1 = 0.f, t2 = 0.f;
#pragma unroll
    for (int j = 0; j < 8; j++) { t1 += a1s[j]; t2 += a2s[j]; }
    float m = t1 * (1.f/256.f);
    float var = t2 * (1.f/256.f) - m*m;
    g_h[i] = (v - m) * rsqrtf(var + 1e-5f) * gam[d] + bet[d];
}

// --------- FP16 mma conv: canvas implicit GEMM, one block per (b, group) ---------
// canvas [16 half2-words][792] (792%32=24 -> conflict-free A frags),
// weights [9 taps][32 oc][18 words]
#define CVSTH 792
#define WSTH  18
#define CONV_SMEM ((16*CVSTH + 9*32*WSTH)*4)
__global__ __launch_bounds__(256, 2) void k_conv(
    const float* __restrict__ cw1, const float* __restrict__ cb1,
    const float* __restrict__ cw2, const float* __restrict__ cb2,
    const float* __restrict__ cw3, const float* __restrict__ cb3,
    float* __restrict__ out)
{
    extern __shared__ unsigned usm[];
    unsigned* cx  = usm;                  // [16][CVSTH]
    unsigned* swt = usm + 16*CVSTH;       // [9][32][WSTH]
    int b = blockIdx.x >> 3, gch = blockIdx.x & 7;
    int tid = threadIdx.x, lane = tid & 31, warp = tid >> 5;
    int grp = lane >> 2, qd = lane & 3;
    const float* hb = g_h + (size_t)b * SSEQ * DDIM;

    for (int i = tid; i < 16*CVSTH; i += 256) cx[i] = 0u;
    __syncthreads();
    // fill canvas: (pixel, half2 channel pair)
    for (int idx = tid; idx < SSEQ*16; idx += 256) {
        int p = idx >> 4, w = idx & 15;
        int cidx = p + 6*(p/22) + 87;
        float2 v = *(const float2*)(hb + (size_t)p*DDIM + gch*32 + 2*w);
        cx[w*CVSTH + cidx] = packh2(v.x, v.y);
    }

    const float* cws[3] = {cw1, cw2, cw3};
    const float* cbs[3] = {cb1, cb2, cb3};

    int mt0 = warp;
#pragma unroll
    for (int half = 0; half < 2; half++) {
        int tA = mt0 + 16*half;
        int pxA0 = tA*16 + grp;
        int pxA1 = pxA0 + 8;
        int pxB0 = (tA + 8)*16 + grp;
        int pxB1 = pxB0 + 8;
        int ciA0 = pxA0 + 6*(pxA0/22) + 87;
        int ciA1 = pxA1 + 6*(pxA1/22) + 87;
        int ciB0 = pxB0 + 6*(pxB0/22) + 87;
        int ciB1 = pxB1 + 6*(pxB1/22) + 87;

        float tot[2][4][4];
#pragma unroll
        for (int p = 0; p < 2; p++)
#pragma unroll
            for (int nt = 0; nt < 4; nt++)
#pragma unroll
                for (int r = 0; r < 4; r++) tot[p][nt][r] = 0.f;

        for (int cv = 0; cv < 3; cv++) {
            int dil = cv + 1;
            __syncthreads();
            // stage weights: src[oc*288 + ic*9 + t] -> swt[t][oc][w=ic/2]
            const float* src = cws[cv] + (size_t)gch * 32 * 288;
            for (int i = tid; i < 32*9*16; i += 256) {
                int oc = i / 144, rem = i - oc*144;
                int t = rem / 16, w = rem - t*16;
                float w0 = src[oc*288 + (2*w)*9 + t];
                float w1 = src[oc*288 + (2*w + 1)*9 + t];
                swt[t*32*WSTH + oc*WSTH + w] = packh2(w0, w1);
            }
            __syncthreads();

            float acc[2][4][4];
#pragma unroll
            for (int p = 0; p < 2; p++)
#pragma unroll
                for (int nt = 0; nt < 4; nt++)
#pragma unroll
                    for (int r = 0; r < 4; r++) acc[p][nt][r] = 0.f;

            for (int t = 0; t < 9; t++) {
                int sh = (t/3 - 1)*dil*28 + (t%3 - 1)*dil;
                const unsigned* wt = swt + t*32*WSTH;
#pragma unroll
                for (int ks = 0; ks < 2; ks++) {
                    const unsigned* r0 = cx + (ks*8 + qd)*CVSTH + sh;
                    const unsigned* r1 = cx + (ks*8 + qd + 4)*CVSTH + sh;
                    unsigned aA0 = r0[ciA0], aA1 = r0[ciA1];
                    unsigned aA2 = r1[ciA0], aA3 = r1[ciA1];
                    unsigned aB0 = r0[ciB0], aB1 = r0[ciB1];
                    unsigned aB2 = r1[ciB0], aB3 = r1[ciB1];
#pragma unroll
                    for (int nt = 0; nt < 4; nt++) {
                        unsigned b0 = wt[(nt*8 + grp)*WSTH + ks*8 + qd];
                        unsigned b1 = wt[(nt*8 + grp)*WSTH + ks*8 + qd + 4];
                        mma_f16_k16(acc[0][nt][0], acc[0][nt][1], acc[0][nt][2], acc[0][nt][3],
                                    aA0, aA1, aA2, aA3, b0, b1);
                        mma_f16_k16(acc[1][nt][0], acc[1][nt][1], acc[1][nt][2], acc[1][nt][3],
                                    aB0, aB1, aB2, aB3, b0, b1);
                    }
                }
            }
#pragma unroll
            for (int nt = 0; nt < 4; nt++) {
                float bi0 = cbs[cv][gch*32 + nt*8 + 2*qd];
                float bi1 = cbs[cv][gch*32 + nt*8 + 2*qd + 1];
#pragma unroll
                for (int p = 0; p < 2; p++) {
                    tot[p][nt][0] += fmaxf(acc[p][nt][0] + bi0, 0.f);
                    tot[p][nt][1] += fmaxf(acc[p][nt][1] + bi1, 0.f);
                    tot[p][nt][2] += fmaxf(acc[p][nt][2] + bi0, 0.f);
                    tot[p][nt][3] += fmaxf(acc[p][nt][3] + bi1, 0.f);
                }
            }
        }

        float* ob = out + (size_t)b * SSEQ * DDIM;
#pragma unroll
        for (int p = 0; p < 2; p++) {
            int px0 = (tA + 8*p)*16 + grp;
            int px1 = px0 + 8;
#pragma unroll
            for (int nt = 0; nt < 4; nt++) {
                int ch = gch*32 + nt*8 + 2*qd;
                if (px0 < SSEQ) {
                    float r0 = hb[(size_t)px0*DDIM + ch];
                    float r1 = hb[(size_t)px0*DDIM + ch + 1];
                    *(float2*)(ob + (size_t)px0*DDIM + ch) =
                        make_float2(0.5f*(r0 + tot[p][nt][0]), 0.5f*(r1 + tot[p][nt][1]));
                }
                if (px1 < SSEQ) {
                    float r2 = hb[(size_t)px1*DDIM + ch];
                    float r3 = hb[(size_t)px1*DDIM + ch + 1];
                    *(float2*)(ob + (size_t)px1*DDIM + ch) =
                        make_float2(0.5f*(r2 + tot[p][nt][2]), 0.5f*(r3 + tot[p][nt][3]));
                }
            }
        }
        __syncthreads();
    }
}

// ------------------------------ launcher ------------------------------
extern "C" void kernel_launch(void* const* d_in, const int* in_sizes, int n_in,
                              void* d_out, int out_size)
{
    const int* x    = (const int*)d_in[0];
    const float* ev   = (const float*)d_in[2];
    const float* px   = (const float*)d_in[3];
    const float* py   = (const float*)d_in[4];
    const float* st   = (const float*)d_in[5];
    const int* tkx = (const int*)d_in[6];
    const int* tky = (const int*)d_in[7];
    const int* tks = (const int*)d_in[8];
    const float* abias = (const float*)d_in[9];
    const float* Wqkv = (const float*)d_in[10];
    const float* bqkv = (const float*)d_in[11];
    const float* Wo   = (const float*)d_in[12];
    const float* bo   = (const float*)d_in[13];
    const float* W1   = (const float*)d_in[14];
    const float* b1   = (const float*)d_in[15];
    const float* W2   = (const float*)d_in[16];
    const float* b2   = (const float*)d_in[17];
    const float* ln1s = (const float*)d_in[18];
    const float* ln1b = (const float*)d_in[19];
    const float* ln2s = (const float*)d_in[20];
    const float* ln2b = (const float*)d_in[21];
    const float* cw1  = (const float*)d_in[22];
    const float* cb1  = (const float*)d_in[23];
    const float* cw2  = (const float*)d_in[24];
    const float* cb2  = (const float*)d_in[25];
    const float* cw3  = (const float*)d_in[26];
    const float* cb3  = (const float*)d_in[27];
    float* out = (float*)d_out;

    float *hP, *qkvP, *t1P, *t2P;
    cudaGetSymbolAddress((void**)&hP,   g_h);
    cudaGetSymbolAddress((void**)&qkvP, g_qkv);
    cudaGetSymbolAddress((void**)&t1P,  g_t1);
    cudaGetSymbolAddress((void**)&t2P,  g_t2);

    cudaFuncSetAttribute(k_attn, cudaFuncAttributeMaxDynamicSharedMemorySize, ATTN_SMEM);
    cudaFuncSetAttribute(k_conv, cudaFuncAttributeMaxDynamicSharedMemorySize, CONV_SMEM);

    k_embed<<<BS_, 256>>>(x, ev, px, py, st, tkx, tky, tks);

    for (int l = 0; l < LNUM; l++) {
        k_gemm<<<dim3(6, 220), 256>>>(hP, Wqkv + (size_t)l*768*256, bqkv + l*768,
                                      qkvP, BS_, 768, 256, 0);
        k_attn<<<BB*HN, 224, ATTN_SMEM>>>(abias);
        k_gemm<<<dim3(2, 220), 256>>>(t1P, Wo + (size_t)l*256*256, bo + l*256,
                                      t2P, BS_, 256, 256, 0);
        k_ln<<<BS_, 256>>>(t2P, ln1s + l*256, ln1b + l*256);
        k_gemm<<<dim3(4, 220), 256>>>(hP, W1 + (size_t)l*512*256, b1 + l*512,
                                      t1P, BS_, 512, 256, 1);
        k_gemm<<<dim3(2, 220), 256>>>(t1P, W2 + (size_t)l*256*512, b2 + l*256,
                                      t2P, BS_, 256, 512, 0);
        k_ln<<<BS_, 256>>>(t2P, ln2s + l*256, ln2b + l*256);
        float* cout = (l == LNUM-1) ? out : hP;
        k_conv<<<BB*HN, 256, CONV_SMEM>>>(cw1 + (size_t)l*256*288, cb1 + l*256,
                                          cw2 + (size_t)l*256*288, cb2 + l*256,
                                          cw3 + (size_t)l*256*288, cb3 + l*256,
                                          cout);
    }
}